// round 1
// baseline (speedup 1.0000x reference)
#include <cuda_runtime.h>

#define T_ 512
#define S_ 512
#define B_ 8
#define D_ 512
#define H_ 8
#define HD_ 64
#define L_ 8
#define F_ 2048

// ---------------- scratch (device globals; no runtime allocation) ----------------
__device__ float g_x  [B_*T_*D_];   // tgt in (B,T,D)
__device__ float g_mem[B_*S_*D_];   // memory in (B,S,D)
__device__ float g_q  [B_*T_*D_];
__device__ float g_k  [B_*S_*D_];
__device__ float g_v  [B_*S_*D_];
__device__ float g_ql [L_*B_*T_*D_];
__device__ float g_sc [B_*H_*T_*T_];
__device__ float g_o  [B_*T_*D_];
__device__ float g_tmp[B_*T_*D_];
__device__ float g_x1 [B_*T_*D_];
__device__ float g_x2 [B_*T_*D_];
__device__ float g_ffn[B_*T_*F_];

// ---------------- (T,B,D) -> (B,T,D) row gather ----------------
__global__ void transpose_tb(const float* __restrict__ in, float* __restrict__ out, int Tdim)
{
    int row = blockIdx.x;             // over Tdim*B rows
    int t = row / B_, b = row - t * B_;
    const float4* src = (const float4*)(in + (size_t)(t * B_ + b) * D_);
    float4* dst = (float4*)(out + (size_t)(b * Tdim + t) * D_);
    dst[threadIdx.x] = src[threadIdx.x];   // 128 threads x float4 = 512 floats
}

// ---------------- shared 64x64 NT tile core: C += A[64,K] * W[64,K]^T ----------------
// 256 threads, 4x4 microtile per thread, BK=16, smem staged k-major (pad 68 keeps
// float4 reads 16B-aligned and conflict-free).
__device__ __forceinline__ void gemm_core_nt(
    const float* __restrict__ A, int lda,
    const float* __restrict__ W, int ldw,
    int K, float acc[4][4],
    float (*As)[68], float (*Ws)[68])
{
    int tid = threadIdx.x;
    int lr = tid >> 2;              // 0..63 row being loaded
    int lk = (tid & 3) << 2;        // 0,4,8,12 k-offset
    int tx = tid & 15, ty = tid >> 4;
    const float* Ap = A + (size_t)lr * lda + lk;
    const float* Wp = W + (size_t)lr * ldw + lk;
    for (int k0 = 0; k0 < K; k0 += 16) {
        float4 a = *(const float4*)(Ap + k0);
        float4 w = *(const float4*)(Wp + k0);
        As[lk+0][lr]=a.x; As[lk+1][lr]=a.y; As[lk+2][lr]=a.z; As[lk+3][lr]=a.w;
        Ws[lk+0][lr]=w.x; Ws[lk+1][lr]=w.y; Ws[lk+2][lr]=w.z; Ws[lk+3][lr]=w.w;
        __syncthreads();
#pragma unroll
        for (int kk = 0; kk < 16; kk++) {
            float4 a4 = *(const float4*)&As[kk][ty << 2];
            float4 w4 = *(const float4*)&Ws[kk][tx << 2];
            float av[4] = {a4.x, a4.y, a4.z, a4.w};
            float wv[4] = {w4.x, w4.y, w4.z, w4.w};
#pragma unroll
            for (int r = 0; r < 4; r++)
#pragma unroll
                for (int c = 0; c < 4; c++)
                    acc[r][c] += av[r] * wv[c];
        }
        __syncthreads();
    }
}

// ---------------- generic dense NT GEMM: C = act(A @ W^T + bias) (+res) ----------------
__global__ __launch_bounds__(256) void gemm_nt(
    const float* __restrict__ A, int lda,
    const float* __restrict__ W, int ldw,
    const float* __restrict__ bias,
    const float* __restrict__ res,
    float* __restrict__ C, int ldc,
    int K, int relu)
{
    __shared__ float As[16][68], Ws[16][68];
    int row0 = blockIdx.y * 64, col0 = blockIdx.x * 64;
    float acc[4][4] = {};
    gemm_core_nt(A + (size_t)row0 * lda, lda, W + (size_t)col0 * ldw, ldw, K, acc, As, Ws);
    int tx = threadIdx.x & 15, ty = threadIdx.x >> 4;
    int col = col0 + (tx << 2);
    float4 bb = make_float4(0.f, 0.f, 0.f, 0.f);
    if (bias) bb = *(const float4*)(bias + col);
#pragma unroll
    for (int r = 0; r < 4; r++) {
        int row = row0 + (ty << 2) + r;
        float4 o = make_float4(acc[r][0] + bb.x, acc[r][1] + bb.y,
                               acc[r][2] + bb.z, acc[r][3] + bb.w);
        if (res) {
            float4 rr = *(const float4*)(res + (size_t)row * ldc + col);
            o.x += rr.x; o.y += rr.y; o.z += rr.z; o.w += rr.w;
        }
        if (relu) {
            o.x = fmaxf(o.x, 0.f); o.y = fmaxf(o.y, 0.f);
            o.z = fmaxf(o.z, 0.f); o.w = fmaxf(o.w, 0.f);
        }
        *(float4*)(C + (size_t)row * ldc + col) = o;
    }
}

// ---------------- ql[l,b,t,h*64+e] = sum_d rel[l][e][d] * q[b,t,h*64+d] ----------------
__global__ __launch_bounds__(256) void ql_kernel(
    const float* __restrict__ q, const float* __restrict__ rel, float* __restrict__ qlb)
{
    __shared__ float As[16][68], Ws[16][68];
    int z = blockIdx.x;                       // l*64 + b*8 + h
    int h = z & 7, b = (z >> 3) & 7, l = z >> 6;
    int i0 = blockIdx.y * 64;
    float acc[4][4] = {};
    gemm_core_nt(q + (size_t)(b * T_ + i0) * D_ + h * HD_, D_,
                 rel + (size_t)l * HD_ * HD_, HD_, HD_, acc, As, Ws);
    int tx = threadIdx.x & 15, ty = threadIdx.x >> 4;
#pragma unroll
    for (int r = 0; r < 4; r++) {
        int i = i0 + (ty << 2) + r;
        *(float4*)(qlb + (size_t)((l * B_ + b) * T_ + i) * D_ + h * HD_ + (tx << 2)) =
            make_float4(acc[r][0], acc[r][1], acc[r][2], acc[r][3]);
    }
}

// ---------------- sa scores: sum_l em[b,l,i,j] * (ql_l[i,:] . k[j,:]) * scale, + mask ----------------
__global__ __launch_bounds__(256) void sa_scores_kernel(
    const float* __restrict__ qlb, const float* __restrict__ k,
    const float* __restrict__ em, const unsigned char* __restrict__ pad,
    float* __restrict__ sc)
{
    __shared__ float As[16][68], Ws[16][68];
    int z = blockIdx.z; int h = z & 7, b = z >> 3;
    int i0 = blockIdx.y * 64, j0 = blockIdx.x * 64;
    int tx = threadIdx.x & 15, ty = threadIdx.x >> 4;
    float acc[4][4] = {};
    for (int l = 0; l < L_; l++) {
        float sl[4][4] = {};
        gemm_core_nt(qlb + (size_t)((l * B_ + b) * T_ + i0) * D_ + h * HD_, D_,
                     k + (size_t)(b * T_ + j0) * D_ + h * HD_, D_, HD_, sl, As, Ws);
#pragma unroll
        for (int r = 0; r < 4; r++) {
            const float4 e4 = *(const float4*)(em +
                (size_t)((b * L_ + l) * T_ + i0 + (ty << 2) + r) * T_ + j0 + (tx << 2));
            acc[r][0] += e4.x * sl[r][0];
            acc[r][1] += e4.y * sl[r][1];
            acc[r][2] += e4.z * sl[r][2];
            acc[r][3] += e4.w * sl[r][3];
        }
    }
#pragma unroll
    for (int r = 0; r < 4; r++) {
        int i = i0 + (ty << 2) + r;
        int j = j0 + (tx << 2);
        const uchar4 m4 = *(const uchar4*)(pad + (size_t)(b * T_ + i) * T_ + j);
        float4 o;
        o.x = m4.x ? -1e9f : acc[r][0] * 0.125f;
        o.y = m4.y ? -1e9f : acc[r][1] * 0.125f;
        o.z = m4.z ? -1e9f : acc[r][2] * 0.125f;
        o.w = m4.w ? -1e9f : acc[r][3] * 0.125f;
        *(float4*)(sc + ((size_t)z * T_ + i) * T_ + j) = o;
    }
}

// ---------------- cross scores: (cq . ck^T) * scale ----------------
__global__ __launch_bounds__(256) void ca_scores_kernel(
    const float* __restrict__ cq, const float* __restrict__ ck, float* __restrict__ sc)
{
    __shared__ float As[16][68], Ws[16][68];
    int z = blockIdx.z; int h = z & 7, b = z >> 3;
    int i0 = blockIdx.y * 64, j0 = blockIdx.x * 64;
    float acc[4][4] = {};
    gemm_core_nt(cq + (size_t)(b * T_ + i0) * D_ + h * HD_, D_,
                 ck + (size_t)(b * S_ + j0) * D_ + h * HD_, D_, HD_, acc, As, Ws);
    int tx = threadIdx.x & 15, ty = threadIdx.x >> 4;
#pragma unroll
    for (int r = 0; r < 4; r++) {
        int i = i0 + (ty << 2) + r;
        *(float4*)(sc + ((size_t)z * T_ + i) * S_ + j0 + (tx << 2)) =
            make_float4(acc[r][0] * 0.125f, acc[r][1] * 0.125f,
                        acc[r][2] * 0.125f, acc[r][3] * 0.125f);
    }
}

// ---------------- row softmax over width 512 ----------------
__global__ void softmax_kernel(float* __restrict__ sc)
{
    __shared__ float red[8];
    int row = blockIdx.x;
    int tid = threadIdx.x;
    float* p = sc + (size_t)row * 512;
    float a0 = p[tid], a1 = p[tid + 256];
    float m = fmaxf(a0, a1);
#pragma unroll
    for (int o = 16; o; o >>= 1) m = fmaxf(m, __shfl_xor_sync(0xffffffffu, m, o));
    if ((tid & 31) == 0) red[tid >> 5] = m;
    __syncthreads();
    m = red[0];
#pragma unroll
    for (int i = 1; i < 8; i++) m = fmaxf(m, red[i]);
    float e0 = __expf(a0 - m), e1 = __expf(a1 - m);
    float s = e0 + e1;
#pragma unroll
    for (int o = 16; o; o >>= 1) s += __shfl_xor_sync(0xffffffffu, s, o);
    __syncthreads();
    if ((tid & 31) == 0) red[tid >> 5] = s;
    __syncthreads();
    s = red[0] + red[1] + red[2] + red[3] + red[4] + red[5] + red[6] + red[7];
    float inv = 1.0f / s;
    p[tid] = e0 * inv;
    p[tid + 256] = e1 * inv;
}

// ---------------- o[b,t,h*64+d] = sum_j attn[z,i,j] * v[b,j,h*64+d]  (NN) ----------------
__global__ __launch_bounds__(256) void attn_v_kernel(
    const float* __restrict__ attn, const float* __restrict__ v,
    float* __restrict__ o, int kdim)
{
    __shared__ float As[16][68], Bs[16][68];
    int z = blockIdx.z; int h = z & 7, b = z >> 3;
    int i0 = blockIdx.y * 64;
    int tid = threadIdx.x;
    int lr = tid >> 2, lk = (tid & 3) << 2;
    int krow = tid >> 4, dcol = (tid & 15) << 2;
    int tx = tid & 15, ty = tid >> 4;
    float acc[4][4] = {};
    const float* Ap = attn + (size_t)z * T_ * kdim + (size_t)(i0 + lr) * kdim + lk;
    const float* Vp = v + (size_t)(b * kdim + krow) * D_ + h * HD_ + dcol;
    for (int k0 = 0; k0 < kdim; k0 += 16) {
        float4 a = *(const float4*)(Ap + k0);
        float4 bb = *(const float4*)(Vp + (size_t)k0 * D_);
        As[lk+0][lr]=a.x; As[lk+1][lr]=a.y; As[lk+2][lr]=a.z; As[lk+3][lr]=a.w;
        *(float4*)&Bs[krow][dcol] = bb;
        __syncthreads();
#pragma unroll
        for (int kk = 0; kk < 16; kk++) {
            float4 a4 = *(const float4*)&As[kk][ty << 2];
            float4 b4 = *(const float4*)&Bs[kk][tx << 2];
            float av[4] = {a4.x, a4.y, a4.z, a4.w};
            float bv[4] = {b4.x, b4.y, b4.z, b4.w};
#pragma unroll
            for (int r = 0; r < 4; r++)
#pragma unroll
                for (int c = 0; c < 4; c++)
                    acc[r][c] += av[r] * bv[c];
        }
        __syncthreads();
    }
#pragma unroll
    for (int r = 0; r < 4; r++) {
        int i = i0 + (ty << 2) + r;
        *(float4*)(o + (size_t)(b * T_ + i) * D_ + h * HD_ + (tx << 2)) =
            make_float4(acc[r][0], acc[r][1], acc[r][2], acc[r][3]);
    }
}

// ---------------- LayerNorm over D=512 (optionally write (T,B,D)-transposed) ----------------
__global__ void ln_kernel(const float* __restrict__ in, const float* __restrict__ sg,
                          const float* __restrict__ bg, float* __restrict__ out, int transpose)
{
    __shared__ float red[4];
    int row = blockIdx.x;      // b*T + t
    int tid = threadIdx.x;     // 128
    const float* x = in + (size_t)row * D_;
    float v[4];
#pragma unroll
    for (int i = 0; i < 4; i++) v[i] = x[tid + i * 128];
    float s = v[0] + v[1] + v[2] + v[3];
#pragma unroll
    for (int o = 16; o; o >>= 1) s += __shfl_xor_sync(0xffffffffu, s, o);
    if ((tid & 31) == 0) red[tid >> 5] = s;
    __syncthreads();
    float mean = (red[0] + red[1] + red[2] + red[3]) * (1.0f / D_);
    __syncthreads();
    float q = 0.f;
#pragma unroll
    for (int i = 0; i < 4; i++) { float d = v[i] - mean; q += d * d; }
#pragma unroll
    for (int o = 16; o; o >>= 1) q += __shfl_xor_sync(0xffffffffu, q, o);
    if ((tid & 31) == 0) red[tid >> 5] = q;
    __syncthreads();
    float var = (red[0] + red[1] + red[2] + red[3]) * (1.0f / D_);
    float inv = rsqrtf(var + 1e-5f);
    int orow = row;
    if (transpose) { int b = row / T_; int t = row - b * T_; orow = t * B_ + b; }
    float* op = out + (size_t)orow * D_;
#pragma unroll
    for (int i = 0; i < 4; i++) {
        int d = tid + i * 128;
        op[d] = (v[i] - mean) * inv * sg[d] + bg[d];
    }
}

// ---------------- launch ----------------
extern "C" void kernel_launch(void* const* d_in, const int* in_sizes, int n_in,
                              void* d_out, int out_size)
{
    const float* tgt       = (const float*)d_in[0];
    const float* em        = (const float*)d_in[1];
    const unsigned char* pad = (const unsigned char*)d_in[2];
    const float* memory    = (const float*)d_in[3];
    const float* sa_q_w    = (const float*)d_in[4];
    const float* sa_q_b    = (const float*)d_in[5];
    const float* sa_k_w    = (const float*)d_in[6];
    const float* sa_k_b    = (const float*)d_in[7];
    const float* sa_v_w    = (const float*)d_in[8];
    const float* sa_v_b    = (const float*)d_in[9];
    const float* sa_rel    = (const float*)d_in[10];
    const float* sa_out_w  = (const float*)d_in[11];
    const float* sa_out_b  = (const float*)d_in[12];
    const float* ca_in_w   = (const float*)d_in[13];
    const float* ca_in_b   = (const float*)d_in[14];
    const float* ca_out_w  = (const float*)d_in[15];
    const float* ca_out_b  = (const float*)d_in[16];
    const float* lin1_w    = (const float*)d_in[17];
    const float* lin1_b    = (const float*)d_in[18];
    const float* lin2_w    = (const float*)d_in[19];
    const float* lin2_b    = (const float*)d_in[20];
    const float* ln1_s     = (const float*)d_in[21];
    const float* ln1_b     = (const float*)d_in[22];
    const float* ln2_s     = (const float*)d_in[23];
    const float* ln2_b     = (const float*)d_in[24];
    const float* ln3_s     = (const float*)d_in[25];
    const float* ln3_b     = (const float*)d_in[26];

    float *x, *mem, *q, *k, *v, *ql, *sc, *o, *tmp, *x1, *x2, *ffn;
    cudaGetSymbolAddress((void**)&x,   g_x);
    cudaGetSymbolAddress((void**)&mem, g_mem);
    cudaGetSymbolAddress((void**)&q,   g_q);
    cudaGetSymbolAddress((void**)&k,   g_k);
    cudaGetSymbolAddress((void**)&v,   g_v);
    cudaGetSymbolAddress((void**)&ql,  g_ql);
    cudaGetSymbolAddress((void**)&sc,  g_sc);
    cudaGetSymbolAddress((void**)&o,   g_o);
    cudaGetSymbolAddress((void**)&tmp, g_tmp);
    cudaGetSymbolAddress((void**)&x1,  g_x1);
    cudaGetSymbolAddress((void**)&x2,  g_x2);
    cudaGetSymbolAddress((void**)&ffn, g_ffn);

    const dim3 gproj(D_ / 64, (B_ * T_) / 64);       // (8, 64)
    const dim3 gattn(T_ / 64, T_ / 64, B_ * H_);     // (8, 8, 64)
    const dim3 gav(1, T_ / 64, B_ * H_);             // (1, 8, 64)

    // --- self-attention ---
    transpose_tb<<<T_ * B_, 128>>>(tgt, x, T_);
    transpose_tb<<<S_ * B_, 128>>>(memory, mem, S_);
    gemm_nt<<<gproj, 256>>>(x, D_, sa_q_w, D_, sa_q_b, nullptr, q, D_, D_, 0);
    gemm_nt<<<gproj, 256>>>(x, D_, sa_k_w, D_, sa_k_b, nullptr, k, D_, D_, 0);
    gemm_nt<<<gproj, 256>>>(x, D_, sa_v_w, D_, sa_v_b, nullptr, v, D_, D_, 0);
    ql_kernel<<<dim3(L_ * B_ * H_, T_ / 64), 256>>>(q, sa_rel, ql);
    sa_scores_kernel<<<gattn, 256>>>(ql, k, em, pad, sc);
    softmax_kernel<<<B_ * H_ * T_, 256>>>(sc);
    attn_v_kernel<<<gav, 256>>>(sc, v, o, T_);
    gemm_nt<<<gproj, 256>>>(o, D_, sa_out_w, D_, sa_out_b, x, tmp, D_, D_, 0);
    ln_kernel<<<B_ * T_, 128>>>(tmp, ln1_s, ln1_b, x1, 0);

    // --- cross-attention ---
    gemm_nt<<<gproj, 256>>>(x1,  D_, ca_in_w,             D_, ca_in_b,          nullptr, q, D_, D_, 0);
    gemm_nt<<<gproj, 256>>>(mem, D_, ca_in_w + D_ * D_,   D_, ca_in_b + D_,     nullptr, k, D_, D_, 0);
    gemm_nt<<<gproj, 256>>>(mem, D_, ca_in_w + 2*D_*D_,   D_, ca_in_b + 2*D_,   nullptr, v, D_, D_, 0);
    ca_scores_kernel<<<dim3(S_ / 64, T_ / 64, B_ * H_), 256>>>(q, k, sc);
    softmax_kernel<<<B_ * H_ * T_, 256>>>(sc);
    attn_v_kernel<<<gav, 256>>>(sc, v, o, S_);
    gemm_nt<<<gproj, 256>>>(o, D_, ca_out_w, D_, ca_out_b, x1, tmp, D_, D_, 0);
    ln_kernel<<<B_ * T_, 128>>>(tmp, ln2_s, ln2_b, x2, 0);

    // --- FFN ---
    gemm_nt<<<dim3(F_ / 64, (B_ * T_) / 64), 256>>>(x2, D_, lin1_w, D_, lin1_b, nullptr, ffn, F_, D_, 1);
    gemm_nt<<<gproj, 256>>>(ffn, F_, lin2_w, F_, lin2_b, x2, tmp, D_, F_, 0);
    ln_kernel<<<B_ * T_, 128>>>(tmp, ln3_s, ln3_b, (float*)d_out, 1);
}

// round 6
// speedup vs baseline: 1.3560x; 1.3560x over previous
#include <cuda_runtime.h>

#define T_ 512
#define S_ 512
#define B_ 8
#define D_ 512
#define H_ 8
#define HD_ 64
#define L_ 8
#define F_ 2048

// ---------------- scratch (device globals; no runtime allocation) ----------------
__device__ float g_x  [B_*T_*D_];
__device__ float g_mem[B_*S_*D_];
__device__ float g_q  [B_*T_*D_];
__device__ float g_k  [B_*S_*D_];
__device__ float g_v  [B_*S_*D_];
__device__ float g_ql [L_*B_*T_*D_];
__device__ float g_sc [B_*H_*T_*T_];
__device__ float g_o  [B_*T_*D_];
__device__ float g_tmp[B_*T_*D_];
__device__ float g_x1 [B_*T_*D_];
__device__ float g_x2 [B_*T_*D_];
__device__ float g_ffn[B_*T_*F_];

__device__ __forceinline__ unsigned totf32(float f) {
    unsigned r; asm("cvt.rna.tf32.f32 %0, %1;" : "=r"(r) : "f"(f)); return r;
}

// smem strides chosen so bank = (8*k + col) & 31 is conflict-free for frag loads
#define ASTRIDE 136   // A: [16][136]  (128 rows of M)
#define WSTRIDE 72    // B: [16][72]   (64 cols of N)

// ---------------- tf32 mma core: one K=16 chunk of a 128x64 tile ----------------
// 8 warps as 4(M) x 2(N); each warp 32x32 via m16n8k8: 2 M-frags x 4 N-frags x 2 k-steps.
// As[k][m] (k-major), Ws[k][n] (k-major). c[mf][nf][4] accumulators.
// A-fragment order (PTX ISA m16n8k8 tf32): a0=(r,q) a1=(r+8,q) a2=(r,q+4) a3=(r+8,q+4)
__device__ __forceinline__ void mma_chunk(
    const float (*As)[ASTRIDE], const float (*Ws)[WSTRIDE],
    int warp_m, int warp_n, int lane, float c[2][4][4])
{
    int r = lane >> 2, q = lane & 3;
#pragma unroll
    for (int ks = 0; ks < 2; ks++) {
        int kb = ks * 8;
        unsigned a[2][4], b[4][2];
#pragma unroll
        for (int mf = 0; mf < 2; mf++) {
            int m0 = warp_m + mf * 16;
            a[mf][0] = __float_as_uint(As[kb + q][m0 + r]);
            a[mf][1] = __float_as_uint(As[kb + q][m0 + r + 8]);
            a[mf][2] = __float_as_uint(As[kb + q + 4][m0 + r]);
            a[mf][3] = __float_as_uint(As[kb + q + 4][m0 + r + 8]);
        }
#pragma unroll
        for (int nf = 0; nf < 4; nf++) {
            int n0 = warp_n + nf * 8;
            b[nf][0] = __float_as_uint(Ws[kb + q][n0 + r]);
            b[nf][1] = __float_as_uint(Ws[kb + q + 4][n0 + r]);
        }
#pragma unroll
        for (int mf = 0; mf < 2; mf++)
#pragma unroll
            for (int nf = 0; nf < 4; nf++)
                asm volatile(
                    "mma.sync.aligned.m16n8k8.row.col.f32.tf32.tf32.f32 "
                    "{%0,%1,%2,%3}, {%4,%5,%6,%7}, {%8,%9}, {%0,%1,%2,%3};"
                    : "+f"(c[mf][nf][0]), "+f"(c[mf][nf][1]),
                      "+f"(c[mf][nf][2]), "+f"(c[mf][nf][3])
                    : "r"(a[mf][0]), "r"(a[mf][1]), "r"(a[mf][2]), "r"(a[mf][3]),
                      "r"(b[nf][0]), "r"(b[nf][1]));
    }
}

// stage A chunk: 128 rows x 16 k (k-major, tf32). 256 threads.
__device__ __forceinline__ void stage_A(const float* __restrict__ Ab, int lda, int k0,
                                        float (*As)[ASTRIDE], int tid)
{
    int lr = tid & 127, lk = (tid >> 7) * 8;
    const float* p = Ab + (size_t)lr * lda + k0 + lk;
    float4 v0 = *(const float4*)(p);
    float4 v1 = *(const float4*)(p + 4);
    As[lk + 0][lr] = __uint_as_float(totf32(v0.x));
    As[lk + 1][lr] = __uint_as_float(totf32(v0.y));
    As[lk + 2][lr] = __uint_as_float(totf32(v0.z));
    As[lk + 3][lr] = __uint_as_float(totf32(v0.w));
    As[lk + 4][lr] = __uint_as_float(totf32(v1.x));
    As[lk + 5][lr] = __uint_as_float(totf32(v1.y));
    As[lk + 6][lr] = __uint_as_float(totf32(v1.z));
    As[lk + 7][lr] = __uint_as_float(totf32(v1.w));
}

// stage W chunk (NT weights W[n][k]): 64 rows x 16 k -> Ws[k][n]. 256 threads.
__device__ __forceinline__ void stage_W(const float* __restrict__ Wb, int ldw, int k0,
                                        float (*Ws)[WSTRIDE], int tid)
{
    int wr = tid & 63, wk = (tid >> 6) * 4;
    const float* p = Wb + (size_t)wr * ldw + k0 + wk;
    float4 v = *(const float4*)(p);
    Ws[wk + 0][wr] = __uint_as_float(totf32(v.x));
    Ws[wk + 1][wr] = __uint_as_float(totf32(v.y));
    Ws[wk + 2][wr] = __uint_as_float(totf32(v.z));
    Ws[wk + 3][wr] = __uint_as_float(totf32(v.w));
}

// ---------------- generic dense NT GEMM: C = act(A @ W^T + bias) (+res) ----------------
__global__ __launch_bounds__(256) void gemm_nt(
    const float* __restrict__ A, int lda,
    const float* __restrict__ W, int ldw,
    const float* __restrict__ bias,
    const float* __restrict__ res,
    float* __restrict__ C, int ldc,
    int K, int relu)
{
    __shared__ float As[16][ASTRIDE], Ws[16][WSTRIDE];
    int tid = threadIdx.x, w = tid >> 5, lane = tid & 31;
    int warp_m = (w >> 1) * 32, warp_n = (w & 1) * 32;
    int row0 = blockIdx.y * 128, col0 = blockIdx.x * 64;
    const float* Ab = A + (size_t)row0 * lda;
    const float* Wb = W + (size_t)col0 * ldw;
    float c[2][4][4] = {};
    for (int k0 = 0; k0 < K; k0 += 16) {
        stage_A(Ab, lda, k0, As, tid);
        stage_W(Wb, ldw, k0, Ws, tid);
        __syncthreads();
        mma_chunk(As, Ws, warp_m, warp_n, lane, c);
        __syncthreads();
    }
    int r = lane >> 2, q = lane & 3;
#pragma unroll
    for (int mf = 0; mf < 2; mf++)
#pragma unroll
    for (int rr = 0; rr < 2; rr++) {
        int row = row0 + warp_m + mf * 16 + r + rr * 8;
#pragma unroll
        for (int nf = 0; nf < 4; nf++) {
            int col = col0 + warp_n + nf * 8 + 2 * q;
            float2 o = make_float2(c[mf][nf][2 * rr], c[mf][nf][2 * rr + 1]);
            if (bias) { float2 bb = *(const float2*)(bias + col); o.x += bb.x; o.y += bb.y; }
            if (res) {
                float2 rv = *(const float2*)(res + (size_t)row * ldc + col);
                o.x += rv.x; o.y += rv.y;
            }
            if (relu) { o.x = fmaxf(o.x, 0.f); o.y = fmaxf(o.y, 0.f); }
            *(float2*)(C + (size_t)row * ldc + col) = o;
        }
    }
}

// ---------------- ql[l,b,t,h*64+e] = q[b,t,h*64+:] @ rel[l]^T ----------------
__global__ __launch_bounds__(256) void ql_kernel(
    const float* __restrict__ qm, const float* __restrict__ rel, float* __restrict__ qlb)
{
    __shared__ float As[16][ASTRIDE], Ws[16][WSTRIDE];
    int z = blockIdx.x;                       // l*64 + b*8 + h
    int h = z & 7, b = (z >> 3) & 7, l = z >> 6;
    int i0 = blockIdx.y * 128;
    int tid = threadIdx.x, w = tid >> 5, lane = tid & 31;
    int warp_m = (w >> 1) * 32, warp_n = (w & 1) * 32;
    const float* Ab = qm + (size_t)(b * T_ + i0) * D_ + h * HD_;
    const float* Wb = rel + (size_t)l * HD_ * HD_;
    float c[2][4][4] = {};
    for (int k0 = 0; k0 < HD_; k0 += 16) {
        stage_A(Ab, D_, k0, As, tid);
        stage_W(Wb, HD_, k0, Ws, tid);
        __syncthreads();
        mma_chunk(As, Ws, warp_m, warp_n, lane, c);
        __syncthreads();
    }
    int r = lane >> 2, q = lane & 3;
    float* Ob = qlb + (size_t)((l * B_ + b) * T_ + i0) * D_ + h * HD_;
#pragma unroll
    for (int mf = 0; mf < 2; mf++)
#pragma unroll
    for (int rr = 0; rr < 2; rr++) {
        int row = warp_m + mf * 16 + r + rr * 8;
#pragma unroll
        for (int nf = 0; nf < 4; nf++) {
            int col = warp_n + nf * 8 + 2 * q;
            *(float2*)(Ob + (size_t)row * D_ + col) =
                make_float2(c[mf][nf][2 * rr], c[mf][nf][2 * rr + 1]);
        }
    }
}

// ---------------- sa scores: sum_l em[b,l,i,j] * (ql_l[i,:] . k[j,:]) * scale, + mask ----------------
__global__ __launch_bounds__(256) void sa_scores_kernel(
    const float* __restrict__ qlb, const float* __restrict__ km,
    const float* __restrict__ em, const unsigned char* __restrict__ pad,
    float* __restrict__ sc)
{
    __shared__ float As[16][ASTRIDE], Ws[16][WSTRIDE];
    int z = blockIdx.z; int h = z & 7, b = z >> 3;
    int i0 = blockIdx.y * 128, j0 = blockIdx.x * 64;
    int tid = threadIdx.x, w = tid >> 5, lane = tid & 31;
    int warp_m = (w >> 1) * 32, warp_n = (w & 1) * 32;
    int r = lane >> 2, q = lane & 3;
    const float* Kb = km + (size_t)(b * T_ + j0) * D_ + h * HD_;
    float acc[2][4][4] = {};
    for (int l = 0; l < L_; l++) {
        const float* Ab = qlb + (size_t)((l * B_ + b) * T_ + i0) * D_ + h * HD_;
        float c[2][4][4] = {};
        for (int k0 = 0; k0 < HD_; k0 += 16) {
            stage_A(Ab, D_, k0, As, tid);
            stage_W(Kb, D_, k0, Ws, tid);
            __syncthreads();
            mma_chunk(As, Ws, warp_m, warp_n, lane, c);
            __syncthreads();
        }
        const float* emb = em + (size_t)(b * L_ + l) * T_ * T_;
#pragma unroll
        for (int mf = 0; mf < 2; mf++)
#pragma unroll
        for (int rr = 0; rr < 2; rr++) {
            int i = i0 + warp_m + mf * 16 + r + rr * 8;
#pragma unroll
            for (int nf = 0; nf < 4; nf++) {
                int j = j0 + warp_n + nf * 8 + 2 * q;
                float2 e = *(const float2*)(emb + (size_t)i * T_ + j);
                acc[mf][nf][2 * rr]     += e.x * c[mf][nf][2 * rr];
                acc[mf][nf][2 * rr + 1] += e.y * c[mf][nf][2 * rr + 1];
            }
        }
    }
#pragma unroll
    for (int mf = 0; mf < 2; mf++)
#pragma unroll
    for (int rr = 0; rr < 2; rr++) {
        int i = i0 + warp_m + mf * 16 + r + rr * 8;
#pragma unroll
        for (int nf = 0; nf < 4; nf++) {
            int j = j0 + warp_n + nf * 8 + 2 * q;
            const unsigned char* pp = pad + (size_t)(b * T_ + i) * T_ + j;
            float2 o;
            o.x = pp[0] ? -1e9f : acc[mf][nf][2 * rr] * 0.125f;
            o.y = pp[1] ? -1e9f : acc[mf][nf][2 * rr + 1] * 0.125f;
            *(float2*)(sc + ((size_t)z * T_ + i) * T_ + j) = o;
        }
    }
}

// ---------------- cross scores: (cq . ck^T) * scale ----------------
__global__ __launch_bounds__(256) void ca_scores_kernel(
    const float* __restrict__ cq, const float* __restrict__ ck, float* __restrict__ sc)
{
    __shared__ float As[16][ASTRIDE], Ws[16][WSTRIDE];
    int z = blockIdx.z; int h = z & 7, b = z >> 3;
    int i0 = blockIdx.y * 128, j0 = blockIdx.x * 64;
    int tid = threadIdx.x, w = tid >> 5, lane = tid & 31;
    int warp_m = (w >> 1) * 32, warp_n = (w & 1) * 32;
    const float* Ab = cq + (size_t)(b * T_ + i0) * D_ + h * HD_;
    const float* Wb = ck + (size_t)(b * S_ + j0) * D_ + h * HD_;
    float c[2][4][4] = {};
    for (int k0 = 0; k0 < HD_; k0 += 16) {
        stage_A(Ab, D_, k0, As, tid);
        stage_W(Wb, D_, k0, Ws, tid);
        __syncthreads();
        mma_chunk(As, Ws, warp_m, warp_n, lane, c);
        __syncthreads();
    }
    int r = lane >> 2, q = lane & 3;
#pragma unroll
    for (int mf = 0; mf < 2; mf++)
#pragma unroll
    for (int rr = 0; rr < 2; rr++) {
        int i = i0 + warp_m + mf * 16 + r + rr * 8;
#pragma unroll
        for (int nf = 0; nf < 4; nf++) {
            int j = j0 + warp_n + nf * 8 + 2 * q;
            *(float2*)(sc + ((size_t)z * T_ + i) * S_ + j) =
                make_float2(c[mf][nf][2 * rr] * 0.125f, c[mf][nf][2 * rr + 1] * 0.125f);
        }
    }
}

// ---------------- row softmax over width 512 ----------------
__global__ void softmax_kernel(float* __restrict__ sc)
{
    __shared__ float red[8];
    int row = blockIdx.x;
    int tid = threadIdx.x;
    float* p = sc + (size_t)row * 512;
    float a0 = p[tid], a1 = p[tid + 256];
    float m = fmaxf(a0, a1);
#pragma unroll
    for (int o = 16; o; o >>= 1) m = fmaxf(m, __shfl_xor_sync(0xffffffffu, m, o));
    if ((tid & 31) == 0) red[tid >> 5] = m;
    __syncthreads();
    m = red[0];
#pragma unroll
    for (int i = 1; i < 8; i++) m = fmaxf(m, red[i]);
    float e0 = __expf(a0 - m), e1 = __expf(a1 - m);
    float s = e0 + e1;
#pragma unroll
    for (int o = 16; o; o >>= 1) s += __shfl_xor_sync(0xffffffffu, s, o);
    __syncthreads();
    if ((tid & 31) == 0) red[tid >> 5] = s;
    __syncthreads();
    s = red[0] + red[1] + red[2] + red[3] + red[4] + red[5] + red[6] + red[7];
    float inv = 1.0f / s;
    p[tid] = e0 * inv;
    p[tid + 256] = e1 * inv;
}

// ---------------- o[b,i,h*64+d] = sum_j attn[z,i,j] * v[b,j,h*64+d]  (NN) ----------------
__global__ __launch_bounds__(256) void attn_v_kernel(
    const float* __restrict__ attn, const float* __restrict__ vm,
    float* __restrict__ o, int kdim)
{
    __shared__ float As[16][ASTRIDE], Ws[16][WSTRIDE];
    int z = blockIdx.z; int h = z & 7, b = z >> 3;
    int i0 = blockIdx.y * 128;
    int tid = threadIdx.x, w = tid >> 5, lane = tid & 31;
    int warp_m = (w >> 1) * 32, warp_n = (w & 1) * 32;
    const float* Ab = attn + (size_t)z * T_ * kdim + (size_t)i0 * kdim;
    const float* Vb = vm + (size_t)b * kdim * D_ + h * HD_;
    int krow = tid >> 4, dcol = (tid & 15) * 4;
    float c[2][4][4] = {};
    for (int k0 = 0; k0 < kdim; k0 += 16) {
        stage_A(Ab, kdim, k0, As, tid);
        {   // stage B NN: Ws[k][n] from v rows (k = j, n = d)
            float4 v = *(const float4*)(Vb + (size_t)(k0 + krow) * D_ + dcol);
            Ws[krow][dcol + 0] = __uint_as_float(totf32(v.x));
            Ws[krow][dcol + 1] = __uint_as_float(totf32(v.y));
            Ws[krow][dcol + 2] = __uint_as_float(totf32(v.z));
            Ws[krow][dcol + 3] = __uint_as_float(totf32(v.w));
        }
        __syncthreads();
        mma_chunk(As, Ws, warp_m, warp_n, lane, c);
        __syncthreads();
    }
    int r = lane >> 2, q = lane & 3;
    float* Ob = o + (size_t)(b * T_ + i0) * D_ + h * HD_;
#pragma unroll
    for (int mf = 0; mf < 2; mf++)
#pragma unroll
    for (int rr = 0; rr < 2; rr++) {
        int row = warp_m + mf * 16 + r + rr * 8;
#pragma unroll
        for (int nf = 0; nf < 4; nf++) {
            int col = warp_n + nf * 8 + 2 * q;
            *(float2*)(Ob + (size_t)row * D_ + col) =
                make_float2(c[mf][nf][2 * rr], c[mf][nf][2 * rr + 1]);
        }
    }
}

// ---------------- (T,B,D) -> (B,T,D) row gather ----------------
__global__ void transpose_tb(const float* __restrict__ in, float* __restrict__ out, int Tdim)
{
    int row = blockIdx.x;
    int t = row / B_, b = row - t * B_;
    const float4* src = (const float4*)(in + (size_t)(t * B_ + b) * D_);
    float4* dst = (float4*)(out + (size_t)(b * Tdim + t) * D_);
    dst[threadIdx.x] = src[threadIdx.x];
}

// ---------------- LayerNorm over D=512 (optionally (T,B,D)-transposed out) ----------------
__global__ void ln_kernel(const float* __restrict__ in, const float* __restrict__ sg,
                          const float* __restrict__ bg, float* __restrict__ out, int transpose)
{
    __shared__ float red[4];
    int row = blockIdx.x;
    int tid = threadIdx.x;
    const float* x = in + (size_t)row * D_;
    float v[4];
#pragma unroll
    for (int i = 0; i < 4; i++) v[i] = x[tid + i * 128];
    float s = v[0] + v[1] + v[2] + v[3];
#pragma unroll
    for (int o = 16; o; o >>= 1) s += __shfl_xor_sync(0xffffffffu, s, o);
    if ((tid & 31) == 0) red[tid >> 5] = s;
    __syncthreads();
    float mean = (red[0] + red[1] + red[2] + red[3]) * (1.0f / D_);
    __syncthreads();
    float qv = 0.f;
#pragma unroll
    for (int i = 0; i < 4; i++) { float d = v[i] - mean; qv += d * d; }
#pragma unroll
    for (int o = 16; o; o >>= 1) qv += __shfl_xor_sync(0xffffffffu, qv, o);
    if ((tid & 31) == 0) red[tid >> 5] = qv;
    __syncthreads();
    float var = (red[0] + red[1] + red[2] + red[3]) * (1.0f / D_);
    float inv = rsqrtf(var + 1e-5f);
    int orow = row;
    if (transpose) { int b = row / T_; int t = row - b * T_; orow = t * B_ + b; }
    float* op = out + (size_t)orow * D_;
#pragma unroll
    for (int i = 0; i < 4; i++) {
        int d = tid + i * 128;
        op[d] = (v[i] - mean) * inv * sg[d] + bg[d];
    }
}

// ---------------- launch ----------------
extern "C" void kernel_launch(void* const* d_in, const int* in_sizes, int n_in,
                              void* d_out, int out_size)
{
    const float* tgt       = (const float*)d_in[0];
    const float* em        = (const float*)d_in[1];
    const unsigned char* pad = (const unsigned char*)d_in[2];
    const float* memory    = (const float*)d_in[3];
    const float* sa_q_w    = (const float*)d_in[4];
    const float* sa_q_b    = (const float*)d_in[5];
    const float* sa_k_w    = (const float*)d_in[6];
    const float* sa_k_b    = (const float*)d_in[7];
    const float* sa_v_w    = (const float*)d_in[8];
    const float* sa_v_b    = (const float*)d_in[9];
    const float* sa_rel    = (const float*)d_in[10];
    const float* sa_out_w  = (const float*)d_in[11];
    const float* sa_out_b  = (const float*)d_in[12];
    const float* ca_in_w   = (const float*)d_in[13];
    const float* ca_in_b   = (const float*)d_in[14];
    const float* ca_out_w  = (const float*)d_in[15];
    const float* ca_out_b  = (const float*)d_in[16];
    const float* lin1_w    = (const float*)d_in[17];
    const float* lin1_b    = (const float*)d_in[18];
    const float* lin2_w    = (const float*)d_in[19];
    const float* lin2_b    = (const float*)d_in[20];
    const float* ln1_s     = (const float*)d_in[21];
    const float* ln1_b     = (const float*)d_in[22];
    const float* ln2_s     = (const float*)d_in[23];
    const float* ln2_b     = (const float*)d_in[24];
    const float* ln3_s     = (const float*)d_in[25];
    const float* ln3_b     = (const float*)d_in[26];

    float *x, *mem, *q, *k, *v, *ql, *sc, *o, *tmp, *x1, *x2, *ffn;
    cudaGetSymbolAddress((void**)&x,   g_x);
    cudaGetSymbolAddress((void**)&mem, g_mem);
    cudaGetSymbolAddress((void**)&q,   g_q);
    cudaGetSymbolAddress((void**)&k,   g_k);
    cudaGetSymbolAddress((void**)&v,   g_v);
    cudaGetSymbolAddress((void**)&ql,  g_ql);
    cudaGetSymbolAddress((void**)&sc,  g_sc);
    cudaGetSymbolAddress((void**)&o,   g_o);
    cudaGetSymbolAddress((void**)&tmp, g_tmp);
    cudaGetSymbolAddress((void**)&x1,  g_x1);
    cudaGetSymbolAddress((void**)&x2,  g_x2);
    cudaGetSymbolAddress((void**)&ffn, g_ffn);

    const dim3 gproj(D_ / 64, (B_ * T_) / 128);       // (8, 32)
    const dim3 gattn(T_ / 64, T_ / 128, B_ * H_);     // (8, 4, 64)
    const dim3 gav(1, T_ / 128, B_ * H_);             // (1, 4, 64)

    // --- self-attention ---
    transpose_tb<<<T_ * B_, 128>>>(tgt, x, T_);
    transpose_tb<<<S_ * B_, 128>>>(memory, mem, S_);
    gemm_nt<<<gproj, 256>>>(x, D_, sa_q_w, D_, sa_q_b, nullptr, q, D_, D_, 0);
    gemm_nt<<<gproj, 256>>>(x, D_, sa_k_w, D_, sa_k_b, nullptr, k, D_, D_, 0);
    gemm_nt<<<gproj, 256>>>(x, D_, sa_v_w, D_, sa_v_b, nullptr, v, D_, D_, 0);
    ql_kernel<<<dim3(L_ * B_ * H_, T_ / 128), 256>>>(q, sa_rel, ql);
    sa_scores_kernel<<<gattn, 256>>>(ql, k, em, pad, sc);
    softmax_kernel<<<B_ * H_ * T_, 256>>>(sc);
    attn_v_kernel<<<gav, 256>>>(sc, v, o, T_);
    gemm_nt<<<gproj, 256>>>(o, D_, sa_out_w, D_, sa_out_b, x, tmp, D_, D_, 0);
    ln_kernel<<<B_ * T_, 128>>>(tmp, ln1_s, ln1_b, x1, 0);

    // --- cross-attention ---
    gemm_nt<<<gproj, 256>>>(x1,  D_, ca_in_w,             D_, ca_in_b,          nullptr, q, D_, D_, 0);
    gemm_nt<<<gproj, 256>>>(mem, D_, ca_in_w + D_ * D_,   D_, ca_in_b + D_,     nullptr, k, D_, D_, 0);
    gemm_nt<<<gproj, 256>>>(mem, D_, ca_in_w + 2*D_*D_,   D_, ca_in_b + 2*D_,   nullptr, v, D_, D_, 0);
    ca_scores_kernel<<<dim3(S_ / 64, T_ / 128, B_ * H_), 256>>>(q, k, sc);
    softmax_kernel<<<B_ * H_ * T_, 256>>>(sc);
    attn_v_kernel<<<gav, 256>>>(sc, v, o, S_);
    gemm_nt<<<gproj, 256>>>(o, D_, ca_out_w, D_, ca_out_b, x1, tmp, D_, D_, 0);
    ln_kernel<<<B_ * T_, 128>>>(tmp, ln2_s, ln2_b, x2, 0);

    // --- FFN ---
    gemm_nt<<<dim3(F_ / 64, (B_ * T_) / 128), 256>>>(x2, D_, lin1_w, D_, lin1_b, nullptr, ffn, F_, D_, 1);
    gemm_nt<<<gproj, 256>>>(ffn, F_, lin2_w, F_, lin2_b, x2, tmp, D_, F_, 0);
    ln_kernel<<<B_ * T_, 128>>>(tmp, ln3_s, ln3_b, (float*)d_out, 1);
}

// round 8
// speedup vs baseline: 1.4849x; 1.0951x over previous
#include <cuda_runtime.h>

#define T_ 512
#define S_ 512
#define B_ 8
#define D_ 512
#define H_ 8
#define HD_ 64
#define L_ 8
#define F_ 2048

// ---------------- scratch (device globals; no runtime allocation) ----------------
__device__ float g_x  [B_*T_*D_];
__device__ float g_mem[B_*S_*D_];
__device__ float g_q  [B_*T_*D_];
__device__ float g_k  [B_*S_*D_];
__device__ float g_v  [B_*S_*D_];
__device__ float g_ql [L_*B_*T_*D_];
__device__ float g_sc [B_*H_*T_*T_];
__device__ float g_o  [B_*T_*D_];
__device__ float g_tmp[B_*T_*D_];
__device__ float g_x1 [B_*T_*D_];
__device__ float g_x2 [B_*T_*D_];
__device__ float g_ffn[B_*T_*F_];

__device__ __forceinline__ unsigned totf32(float f) {
    unsigned r; asm("cvt.rna.tf32.f32 %0, %1;" : "=r"(r) : "f"(f)); return r;
}
__device__ __forceinline__ float cvt(float f) { return __uint_as_float(totf32(f)); }

// smem strides chosen so bank = (8*k + col) & 31 is conflict-free for frag loads
#define ASTRIDE 136   // A: [16][136]  (128 rows of M)
#define WSTRIDE 72    // B: [16][72]   (64 cols of N)

// ---------------- prefetch structs (register staging for double buffering) ----------------
struct PA { float4 a, b; };
struct PW { float4 a; };

__device__ __forceinline__ void ldgA(const float* __restrict__ Ab, int lda, int k0,
                                     int tid, PA& p)
{
    int lr = tid & 127, lk = (tid >> 7) * 8;
    const float* ptr = Ab + (size_t)lr * lda + k0 + lk;
    p.a = *(const float4*)(ptr);
    p.b = *(const float4*)(ptr + 4);
}
__device__ __forceinline__ void stsA(const PA& p, float (*As)[ASTRIDE], int tid)
{
    int lr = tid & 127, lk = (tid >> 7) * 8;
    As[lk + 0][lr] = cvt(p.a.x); As[lk + 1][lr] = cvt(p.a.y);
    As[lk + 2][lr] = cvt(p.a.z); As[lk + 3][lr] = cvt(p.a.w);
    As[lk + 4][lr] = cvt(p.b.x); As[lk + 5][lr] = cvt(p.b.y);
    As[lk + 6][lr] = cvt(p.b.z); As[lk + 7][lr] = cvt(p.b.w);
}
__device__ __forceinline__ void ldgW(const float* __restrict__ Wb, int ldw, int k0,
                                     int tid, PW& p)
{
    int wr = tid & 63, wk = (tid >> 6) * 4;
    p.a = *(const float4*)(Wb + (size_t)wr * ldw + k0 + wk);
}
__device__ __forceinline__ void stsW(const PW& p, float (*Ws)[WSTRIDE], int tid)
{
    int wr = tid & 63, wk = (tid >> 6) * 4;
    Ws[wk + 0][wr] = cvt(p.a.x); Ws[wk + 1][wr] = cvt(p.a.y);
    Ws[wk + 2][wr] = cvt(p.a.z); Ws[wk + 3][wr] = cvt(p.a.w);
}
// NN staging for attn_v: Ws[k][n] from v rows (k = j, n = d)
__device__ __forceinline__ void ldgWnn(const float* __restrict__ Vb, int ldv, int k0,
                                       int tid, PW& p)
{
    int krow = tid >> 4, dcol = (tid & 15) * 4;
    p.a = *(const float4*)(Vb + (size_t)(k0 + krow) * ldv + dcol);
}
__device__ __forceinline__ void stsWnn(const PW& p, float (*Ws)[WSTRIDE], int tid)
{
    int krow = tid >> 4, dcol = (tid & 15) * 4;
    Ws[krow][dcol + 0] = cvt(p.a.x); Ws[krow][dcol + 1] = cvt(p.a.y);
    Ws[krow][dcol + 2] = cvt(p.a.z); Ws[krow][dcol + 3] = cvt(p.a.w);
}

// ---------------- tf32 mma core: one K=16 chunk of a 128x64 tile ----------------
// 8 warps as 4(M) x 2(N); each warp 32x32 via m16n8k8: 2 M-frags x 4 N-frags x 2 k-steps.
// A-fragment order (PTX ISA m16n8k8 tf32): a0=(r,q) a1=(r+8,q) a2=(r,q+4) a3=(r+8,q+4)
__device__ __forceinline__ void mma_chunk(
    const float (*As)[ASTRIDE], const float (*Ws)[WSTRIDE],
    int warp_m, int warp_n, int lane, float c[2][4][4])
{
    int r = lane >> 2, q = lane & 3;
#pragma unroll
    for (int ks = 0; ks < 2; ks++) {
        int kb = ks * 8;
        unsigned a[2][4], b[4][2];
#pragma unroll
        for (int mf = 0; mf < 2; mf++) {
            int m0 = warp_m + mf * 16;
            a[mf][0] = __float_as_uint(As[kb + q][m0 + r]);
            a[mf][1] = __float_as_uint(As[kb + q][m0 + r + 8]);
            a[mf][2] = __float_as_uint(As[kb + q + 4][m0 + r]);
            a[mf][3] = __float_as_uint(As[kb + q + 4][m0 + r + 8]);
        }
#pragma unroll
        for (int nf = 0; nf < 4; nf++) {
            int n0 = warp_n + nf * 8;
            b[nf][0] = __float_as_uint(Ws[kb + q][n0 + r]);
            b[nf][1] = __float_as_uint(Ws[kb + q + 4][n0 + r]);
        }
#pragma unroll
        for (int mf = 0; mf < 2; mf++)
#pragma unroll
            for (int nf = 0; nf < 4; nf++)
                asm volatile(
                    "mma.sync.aligned.m16n8k8.row.col.f32.tf32.tf32.f32 "
                    "{%0,%1,%2,%3}, {%4,%5,%6,%7}, {%8,%9}, {%0,%1,%2,%3};"
                    : "+f"(c[mf][nf][0]), "+f"(c[mf][nf][1]),
                      "+f"(c[mf][nf][2]), "+f"(c[mf][nf][3])
                    : "r"(a[mf][0]), "r"(a[mf][1]), "r"(a[mf][2]), "r"(a[mf][3]),
                      "r"(b[nf][0]), "r"(b[nf][1]));
    }
}

// ---------------- generic dense NT GEMM: C = act(A @ W^T + bias) (+res) ----------------
__global__ __launch_bounds__(256) void gemm_nt(
    const float* __restrict__ A, int lda,
    const float* __restrict__ W, int ldw,
    const float* __restrict__ bias,
    const float* __restrict__ res,
    float* __restrict__ C, int ldc,
    int K, int relu)
{
    __shared__ float As[2][16][ASTRIDE], Ws[2][16][WSTRIDE];
    int tid = threadIdx.x, w = tid >> 5, lane = tid & 31;
    int warp_m = (w >> 1) * 32, warp_n = (w & 1) * 32;
    int row0 = blockIdx.y * 128, col0 = blockIdx.x * 64;
    const float* Ab = A + (size_t)row0 * lda;
    const float* Wb = W + (size_t)col0 * ldw;
    float c[2][4][4] = {};
    PA pa; PW pw;
    ldgA(Ab, lda, 0, tid, pa); ldgW(Wb, ldw, 0, tid, pw);
    stsA(pa, As[0], tid); stsW(pw, Ws[0], tid);
    __syncthreads();
    int nch = K >> 4;
    for (int ch = 0; ch < nch; ch++) {
        int nxt = ch + 1;
        if (nxt < nch) { ldgA(Ab, lda, nxt << 4, tid, pa); ldgW(Wb, ldw, nxt << 4, tid, pw); }
        mma_chunk(As[ch & 1], Ws[ch & 1], warp_m, warp_n, lane, c);
        if (nxt < nch) {
            stsA(pa, As[nxt & 1], tid); stsW(pw, Ws[nxt & 1], tid);
            __syncthreads();
        }
    }
    int r = lane >> 2, q = lane & 3;
#pragma unroll
    for (int mf = 0; mf < 2; mf++)
#pragma unroll
    for (int rr = 0; rr < 2; rr++) {
        int row = row0 + warp_m + mf * 16 + r + rr * 8;
#pragma unroll
        for (int nf = 0; nf < 4; nf++) {
            int col = col0 + warp_n + nf * 8 + 2 * q;
            float2 o = make_float2(c[mf][nf][2 * rr], c[mf][nf][2 * rr + 1]);
            if (bias) { float2 bb = *(const float2*)(bias + col); o.x += bb.x; o.y += bb.y; }
            if (res) {
                float2 rv = *(const float2*)(res + (size_t)row * ldc + col);
                o.x += rv.x; o.y += rv.y;
            }
            if (relu) { o.x = fmaxf(o.x, 0.f); o.y = fmaxf(o.y, 0.f); }
            *(float2*)(C + (size_t)row * ldc + col) = o;
        }
    }
}

// ---------------- ql[l,b,t,h*64+e] = q[b,t,h*64+:] @ rel[l]^T ----------------
__global__ __launch_bounds__(256) void ql_kernel(
    const float* __restrict__ qm, const float* __restrict__ rel, float* __restrict__ qlb)
{
    __shared__ float As[2][16][ASTRIDE], Ws[2][16][WSTRIDE];
    int z = blockIdx.x;                       // l*64 + b*8 + h
    int h = z & 7, b = (z >> 3) & 7, l = z >> 6;
    int i0 = blockIdx.y * 128;
    int tid = threadIdx.x, w = tid >> 5, lane = tid & 31;
    int warp_m = (w >> 1) * 32, warp_n = (w & 1) * 32;
    const float* Ab = qm + (size_t)(b * T_ + i0) * D_ + h * HD_;
    const float* Wb = rel + (size_t)l * HD_ * HD_;
    float c[2][4][4] = {};
    PA pa; PW pw;
    ldgA(Ab, D_, 0, tid, pa); ldgW(Wb, HD_, 0, tid, pw);
    stsA(pa, As[0], tid); stsW(pw, Ws[0], tid);
    __syncthreads();
    const int nch = HD_ / 16;
    for (int ch = 0; ch < nch; ch++) {
        int nxt = ch + 1;
        if (nxt < nch) { ldgA(Ab, D_, nxt << 4, tid, pa); ldgW(Wb, HD_, nxt << 4, tid, pw); }
        mma_chunk(As[ch & 1], Ws[ch & 1], warp_m, warp_n, lane, c);
        if (nxt < nch) {
            stsA(pa, As[nxt & 1], tid); stsW(pw, Ws[nxt & 1], tid);
            __syncthreads();
        }
    }
    int r = lane >> 2, q = lane & 3;
    float* Ob = qlb + (size_t)((l * B_ + b) * T_ + i0) * D_ + h * HD_;
#pragma unroll
    for (int mf = 0; mf < 2; mf++)
#pragma unroll
    for (int rr = 0; rr < 2; rr++) {
        int row = warp_m + mf * 16 + r + rr * 8;
#pragma unroll
        for (int nf = 0; nf < 4; nf++) {
            int col = warp_n + nf * 8 + 2 * q;
            *(float2*)(Ob + (size_t)row * D_ + col) =
                make_float2(c[mf][nf][2 * rr], c[mf][nf][2 * rr + 1]);
        }
    }
}

// ---------------- sa scores: sum_l em[b,l,i,j] * (ql_l[i,:] . k[j,:]) * scale, + mask ----------------
// K tile (Ws) is invariant across l: stage its 4 chunks ONCE. Pipeline A flat over 32 (l,k) chunks.
__global__ __launch_bounds__(256) void sa_scores_kernel(
    const float* __restrict__ qlb, const float* __restrict__ km,
    const float* __restrict__ em, const unsigned char* __restrict__ pad,
    float* __restrict__ sc)
{
    __shared__ float As[2][16][ASTRIDE], Ws4[4][16][WSTRIDE];
    int z = blockIdx.z; int h = z & 7, b = z >> 3;
    int i0 = blockIdx.y * 128, j0 = blockIdx.x * 64;
    int tid = threadIdx.x, w = tid >> 5, lane = tid & 31;
    int warp_m = (w >> 1) * 32, warp_n = (w & 1) * 32;
    int r = lane >> 2, q = lane & 3;
    const float* Kb = km + (size_t)(b * T_ + j0) * D_ + h * HD_;
#pragma unroll
    for (int kc = 0; kc < 4; kc++) {
        PW pw; ldgW(Kb, D_, kc << 4, tid, pw); stsW(pw, Ws4[kc], tid);
    }
    auto Abase = [&](int l) {
        return qlb + (size_t)((l * B_ + b) * T_ + i0) * D_ + h * HD_;
    };
    PA pa;
    ldgA(Abase(0), D_, 0, tid, pa);
    stsA(pa, As[0], tid);
    __syncthreads();

    float acc[2][4][4] = {};
    int cc = 0;
    for (int l = 0; l < L_; l++) {
        float c[2][4][4] = {};
#pragma unroll
        for (int kc = 0; kc < 4; kc++) {
            bool have_next = !(l == L_ - 1 && kc == 3);
            if (have_next) {
                int nl = (kc == 3) ? l + 1 : l;
                int nk = (kc == 3) ? 0 : kc + 1;
                ldgA(Abase(nl), D_, nk << 4, tid, pa);
            }
            mma_chunk(As[cc & 1], Ws4[kc], warp_m, warp_n, lane, c);
            if (have_next) {
                stsA(pa, As[(cc + 1) & 1], tid);
                __syncthreads();
            }
            cc++;
        }
        const float* emb = em + (size_t)(b * L_ + l) * T_ * T_;
#pragma unroll
        for (int mf = 0; mf < 2; mf++)
#pragma unroll
        for (int rr = 0; rr < 2; rr++) {
            int i = i0 + warp_m + mf * 16 + r + rr * 8;
#pragma unroll
            for (int nf = 0; nf < 4; nf++) {
                int j = j0 + warp_n + nf * 8 + 2 * q;
                float2 e = *(const float2*)(emb + (size_t)i * T_ + j);
                acc[mf][nf][2 * rr]     += e.x * c[mf][nf][2 * rr];
                acc[mf][nf][2 * rr + 1] += e.y * c[mf][nf][2 * rr + 1];
            }
        }
    }
#pragma unroll
    for (int mf = 0; mf < 2; mf++)
#pragma unroll
    for (int rr = 0; rr < 2; rr++) {
        int i = i0 + warp_m + mf * 16 + r + rr * 8;
#pragma unroll
        for (int nf = 0; nf < 4; nf++) {
            int j = j0 + warp_n + nf * 8 + 2 * q;
            const unsigned char* pp = pad + (size_t)(b * T_ + i) * T_ + j;
            float2 o;
            o.x = pp[0] ? -1e9f : acc[mf][nf][2 * rr] * 0.125f;
            o.y = pp[1] ? -1e9f : acc[mf][nf][2 * rr + 1] * 0.125f;
            *(float2*)(sc + ((size_t)z * T_ + i) * T_ + j) = o;
        }
    }
}

// ---------------- cross scores: (cq . ck^T) * scale ----------------
__global__ __launch_bounds__(256) void ca_scores_kernel(
    const float* __restrict__ cq, const float* __restrict__ ck, float* __restrict__ sc)
{
    __shared__ float As[2][16][ASTRIDE], Ws[2][16][WSTRIDE];
    int z = blockIdx.z; int h = z & 7, b = z >> 3;
    int i0 = blockIdx.y * 128, j0 = blockIdx.x * 64;
    int tid = threadIdx.x, w = tid >> 5, lane = tid & 31;
    int warp_m = (w >> 1) * 32, warp_n = (w & 1) * 32;
    const float* Ab = cq + (size_t)(b * T_ + i0) * D_ + h * HD_;
    const float* Wb = ck + (size_t)(b * S_ + j0) * D_ + h * HD_;
    float c[2][4][4] = {};
    PA pa; PW pw;
    ldgA(Ab, D_, 0, tid, pa); ldgW(Wb, D_, 0, tid, pw);
    stsA(pa, As[0], tid); stsW(pw, Ws[0], tid);
    __syncthreads();
    const int nch = HD_ / 16;
    for (int ch = 0; ch < nch; ch++) {
        int nxt = ch + 1;
        if (nxt < nch) { ldgA(Ab, D_, nxt << 4, tid, pa); ldgW(Wb, D_, nxt << 4, tid, pw); }
        mma_chunk(As[ch & 1], Ws[ch & 1], warp_m, warp_n, lane, c);
        if (nxt < nch) {
            stsA(pa, As[nxt & 1], tid); stsW(pw, Ws[nxt & 1], tid);
            __syncthreads();
        }
    }
    int r = lane >> 2, q = lane & 3;
#pragma unroll
    for (int mf = 0; mf < 2; mf++)
#pragma unroll
    for (int rr = 0; rr < 2; rr++) {
        int i = i0 + warp_m + mf * 16 + r + rr * 8;
#pragma unroll
        for (int nf = 0; nf < 4; nf++) {
            int j = j0 + warp_n + nf * 8 + 2 * q;
            *(float2*)(sc + ((size_t)z * T_ + i) * S_ + j) =
                make_float2(c[mf][nf][2 * rr] * 0.125f, c[mf][nf][2 * rr + 1] * 0.125f);
        }
    }
}

// ---------------- row softmax over width 512 ----------------
__global__ void softmax_kernel(float* __restrict__ sc)
{
    __shared__ float red[8];
    int row = blockIdx.x;
    int tid = threadIdx.x;
    float* p = sc + (size_t)row * 512;
    float a0 = p[tid], a1 = p[tid + 256];
    float m = fmaxf(a0, a1);
#pragma unroll
    for (int o = 16; o; o >>= 1) m = fmaxf(m, __shfl_xor_sync(0xffffffffu, m, o));
    if ((tid & 31) == 0) red[tid >> 5] = m;
    __syncthreads();
    m = red[0];
#pragma unroll
    for (int i = 1; i < 8; i++) m = fmaxf(m, red[i]);
    float e0 = __expf(a0 - m), e1 = __expf(a1 - m);
    float s = e0 + e1;
#pragma unroll
    for (int o = 16; o; o >>= 1) s += __shfl_xor_sync(0xffffffffu, s, o);
    __syncthreads();
    if ((tid & 31) == 0) red[tid >> 5] = s;
    __syncthreads();
    s = red[0] + red[1] + red[2] + red[3] + red[4] + red[5] + red[6] + red[7];
    float inv = 1.0f / s;
    p[tid] = e0 * inv;
    p[tid + 256] = e1 * inv;
}

// ---------------- o[b,i,h*64+d] = sum_j attn[z,i,j] * v[b,j,h*64+d]  (NN) ----------------
__global__ __launch_bounds__(256) void attn_v_kernel(
    const float* __restrict__ attn, const float* __restrict__ vm,
    float* __restrict__ o, int kdim)
{
    __shared__ float As[2][16][ASTRIDE], Ws[2][16][WSTRIDE];
    int z = blockIdx.z; int h = z & 7, b = z >> 3;
    int i0 = blockIdx.y * 128;
    int tid = threadIdx.x, w = tid >> 5, lane = tid & 31;
    int warp_m = (w >> 1) * 32, warp_n = (w & 1) * 32;
    const float* Ab = attn + (size_t)z * T_ * kdim + (size_t)i0 * kdim;
    const float* Vb = vm + (size_t)b * kdim * D_ + h * HD_;
    float c[2][4][4] = {};
    PA pa; PW pw;
    ldgA(Ab, kdim, 0, tid, pa); ldgWnn(Vb, D_, 0, tid, pw);
    stsA(pa, As[0], tid); stsWnn(pw, Ws[0], tid);
    __syncthreads();
    int nch = kdim >> 4;
    for (int ch = 0; ch < nch; ch++) {
        int nxt = ch + 1;
        if (nxt < nch) { ldgA(Ab, kdim, nxt << 4, tid, pa); ldgWnn(Vb, D_, nxt << 4, tid, pw); }
        mma_chunk(As[ch & 1], Ws[ch & 1], warp_m, warp_n, lane, c);
        if (nxt < nch) {
            stsA(pa, As[nxt & 1], tid); stsWnn(pw, Ws[nxt & 1], tid);
            __syncthreads();
        }
    }
    int r = lane >> 2, q = lane & 3;
    float* Ob = o + (size_t)(b * T_ + i0) * D_ + h * HD_;
#pragma unroll
    for (int mf = 0; mf < 2; mf++)
#pragma unroll
    for (int rr = 0; rr < 2; rr++) {
        int row = warp_m + mf * 16 + r + rr * 8;
#pragma unroll
        for (int nf = 0; nf < 4; nf++) {
            int col = warp_n + nf * 8 + 2 * q;
            *(float2*)(Ob + (size_t)row * D_ + col) =
                make_float2(c[mf][nf][2 * rr], c[mf][nf][2 * rr + 1]);
        }
    }
}

// ---------------- (T,B,D) -> (B,T,D) row gather ----------------
__global__ void transpose_tb(const float* __restrict__ in, float* __restrict__ out, int Tdim)
{
    int row = blockIdx.x;
    int t = row / B_, b = row - t * B_;
    const float4* src = (const float4*)(in + (size_t)(t * B_ + b) * D_);
    float4* dst = (float4*)(out + (size_t)(b * Tdim + t) * D_);
    dst[threadIdx.x] = src[threadIdx.x];
}

// ---------------- LayerNorm over D=512 (optionally (T,B,D)-transposed out) ----------------
__global__ void ln_kernel(const float* __restrict__ in, const float* __restrict__ sg,
                          const float* __restrict__ bg, float* __restrict__ out, int transpose)
{
    __shared__ float red[4];
    int row = blockIdx.x;
    int tid = threadIdx.x;
    const float* x = in + (size_t)row * D_;
    float v[4];
#pragma unroll
    for (int i = 0; i < 4; i++) v[i] = x[tid + i * 128];
    float s = v[0] + v[1] + v[2] + v[3];
#pragma unroll
    for (int o = 16; o; o >>= 1) s += __shfl_xor_sync(0xffffffffu, s, o);
    if ((tid & 31) == 0) red[tid >> 5] = s;
    __syncthreads();
    float mean = (red[0] + red[1] + red[2] + red[3]) * (1.0f / D_);
    __syncthreads();
    float qv = 0.f;
#pragma unroll
    for (int i = 0; i < 4; i++) { float d = v[i] - mean; qv += d * d; }
#pragma unroll
    for (int o = 16; o; o >>= 1) qv += __shfl_xor_sync(0xffffffffu, qv, o);
    if ((tid & 31) == 0) red[tid >> 5] = qv;
    __syncthreads();
    float var = (red[0] + red[1] + red[2] + red[3]) * (1.0f / D_);
    float inv = rsqrtf(var + 1e-5f);
    int orow = row;
    if (transpose) { int b = row / T_; int t = row - b * T_; orow = t * B_ + b; }
    float* op = out + (size_t)orow * D_;
#pragma unroll
    for (int i = 0; i < 4; i++) {
        int d = tid + i * 128;
        op[d] = (v[i] - mean) * inv * sg[d] + bg[d];
    }
}

// ---------------- launch ----------------
extern "C" void kernel_launch(void* const* d_in, const int* in_sizes, int n_in,
                              void* d_out, int out_size)
{
    const float* tgt       = (const float*)d_in[0];
    const float* em        = (const float*)d_in[1];
    const unsigned char* pad = (const unsigned char*)d_in[2];
    const float* memory    = (const float*)d_in[3];
    const float* sa_q_w    = (const float*)d_in[4];
    const float* sa_q_b    = (const float*)d_in[5];
    const float* sa_k_w    = (const float*)d_in[6];
    const float* sa_k_b    = (const float*)d_in[7];
    const float* sa_v_w    = (const float*)d_in[8];
    const float* sa_v_b    = (const float*)d_in[9];
    const float* sa_rel    = (const float*)d_in[10];
    const float* sa_out_w  = (const float*)d_in[11];
    const float* sa_out_b  = (const float*)d_in[12];
    const float* ca_in_w   = (const float*)d_in[13];
    const float* ca_in_b   = (const float*)d_in[14];
    const float* ca_out_w  = (const float*)d_in[15];
    const float* ca_out_b  = (const float*)d_in[16];
    const float* lin1_w    = (const float*)d_in[17];
    const float* lin1_b    = (const float*)d_in[18];
    const float* lin2_w    = (const float*)d_in[19];
    const float* lin2_b    = (const float*)d_in[20];
    const float* ln1_s     = (const float*)d_in[21];
    const float* ln1_b     = (const float*)d_in[22];
    const float* ln2_s     = (const float*)d_in[23];
    const float* ln2_b     = (const float*)d_in[24];
    const float* ln3_s     = (const float*)d_in[25];
    const float* ln3_b     = (const float*)d_in[26];

    float *x, *mem, *q, *k, *v, *ql, *sc, *o, *tmp, *x1, *x2, *ffn;
    cudaGetSymbolAddress((void**)&x,   g_x);
    cudaGetSymbolAddress((void**)&mem, g_mem);
    cudaGetSymbolAddress((void**)&q,   g_q);
    cudaGetSymbolAddress((void**)&k,   g_k);
    cudaGetSymbolAddress((void**)&v,   g_v);
    cudaGetSymbolAddress((void**)&ql,  g_ql);
    cudaGetSymbolAddress((void**)&sc,  g_sc);
    cudaGetSymbolAddress((void**)&o,   g_o);
    cudaGetSymbolAddress((void**)&tmp, g_tmp);
    cudaGetSymbolAddress((void**)&x1,  g_x1);
    cudaGetSymbolAddress((void**)&x2,  g_x2);
    cudaGetSymbolAddress((void**)&ffn, g_ffn);

    const dim3 gproj(D_ / 64, (B_ * T_) / 128);       // (8, 32)
    const dim3 gattn(T_ / 64, T_ / 128, B_ * H_);     // (8, 4, 64)
    const dim3 gav(1, T_ / 128, B_ * H_);             // (1, 4, 64)

    // --- self-attention ---
    transpose_tb<<<T_ * B_, 128>>>(tgt, x, T_);
    transpose_tb<<<S_ * B_, 128>>>(memory, mem, S_);
    gemm_nt<<<gproj, 256>>>(x, D_, sa_q_w, D_, sa_q_b, nullptr, q, D_, D_, 0);
    gemm_nt<<<gproj, 256>>>(x, D_, sa_k_w, D_, sa_k_b, nullptr, k, D_, D_, 0);
    gemm_nt<<<gproj, 256>>>(x, D_, sa_v_w, D_, sa_v_b, nullptr, v, D_, D_, 0);
    ql_kernel<<<dim3(L_ * B_ * H_, T_ / 128), 256>>>(q, sa_rel, ql);
    sa_scores_kernel<<<gattn, 256>>>(ql, k, em, pad, sc);
    softmax_kernel<<<B_ * H_ * T_, 256>>>(sc);
    attn_v_kernel<<<gav, 256>>>(sc, v, o, T_);
    gemm_nt<<<gproj, 256>>>(o, D_, sa_out_w, D_, sa_out_b, x, tmp, D_, D_, 0);
    ln_kernel<<<B_ * T_, 128>>>(tmp, ln1_s, ln1_b, x1, 0);

    // --- cross-attention ---
    gemm_nt<<<gproj, 256>>>(x1,  D_, ca_in_w,             D_, ca_in_b,          nullptr, q, D_, D_, 0);
    gemm_nt<<<gproj, 256>>>(mem, D_, ca_in_w + D_ * D_,   D_, ca_in_b + D_,     nullptr, k, D_, D_, 0);
    gemm_nt<<<gproj, 256>>>(mem, D_, ca_in_w + 2*D_*D_,   D_, ca_in_b + 2*D_,   nullptr, v, D_, D_, 0);
    ca_scores_kernel<<<dim3(S_ / 64, T_ / 128, B_ * H_), 256>>>(q, k, sc);
    softmax_kernel<<<B_ * H_ * T_, 256>>>(sc);
    attn_v_kernel<<<gav, 256>>>(sc, v, o, S_);
    gemm_nt<<<gproj, 256>>>(o, D_, ca_out_w, D_, ca_out_b, x1, tmp, D_, D_, 0);
    ln_kernel<<<B_ * T_, 128>>>(tmp, ln2_s, ln2_b, x2, 0);

    // --- FFN ---
    gemm_nt<<<dim3(F_ / 64, (B_ * T_) / 128), 256>>>(x2, D_, lin1_w, D_, lin1_b, nullptr, ffn, F_, D_, 1);
    gemm_nt<<<gproj, 256>>>(ffn, F_, lin2_w, F_, lin2_b, x2, tmp, D_, F_, 0);
    ln_kernel<<<B_ * T_, 128>>>(tmp, ln3_s, ln3_b, (float*)d_out, 1);
}

// round 9
// speedup vs baseline: 2.3255x; 1.5661x over previous
#include <cuda_runtime.h>

#define T_ 512
#define S_ 512
#define B_ 8
#define D_ 512
#define H_ 8
#define HD_ 64
#define L_ 8
#define F_ 2048

// ---------------- scratch (device globals; no runtime allocation) ----------------
__device__ float g_x  [B_*T_*D_];     // raw (B,T,D) tgt  (residual use)
__device__ float g_xc [B_*T_*D_];     // tf32-rounded copy (GEMM input)
__device__ float g_memc[B_*S_*D_];    // rounded memory (B,S,D)
__device__ float g_q  [B_*T_*D_];     // rounded projection outputs
__device__ float g_k  [B_*S_*D_];
__device__ float g_v  [B_*S_*D_];
__device__ float g_ql [L_*B_*T_*D_];
__device__ float g_sc [B_*H_*T_*T_];
__device__ float g_o  [B_*T_*D_];
__device__ float g_tmp[B_*T_*D_];
__device__ float g_x1 [B_*T_*D_];
__device__ float g_x1c[B_*T_*D_];
__device__ float g_x2 [B_*T_*D_];
__device__ float g_x2c[B_*T_*D_];
__device__ float g_ffn[B_*T_*F_];
__device__ float g_wts[4227072];      // rounded weights, offsets below

#define WQ_OFF   0
#define WK_OFF   262144
#define WV_OFF   524288
#define WO_OFF   786432
#define WCA_OFF  1048576
#define WCAO_OFF 1835008
#define WL1_OFF  2097152
#define WL2_OFF  3145728
#define WREL_OFF 4194304

__device__ __forceinline__ float cvt(float f) {
    unsigned r; asm("cvt.rna.tf32.f32 %0, %1;" : "=r"(r) : "f"(f));
    return __uint_as_float(r);
}

// ---------------- cp.async helpers ----------------
__device__ __forceinline__ void cp16(unsigned dst, const void* src) {
    asm volatile("cp.async.ca.shared.global [%0], [%1], 16;" :: "r"(dst), "l"(src));
}
#define CP_COMMIT() asm volatile("cp.async.commit_group;" ::: "memory")
#define CP_WAIT0()  asm volatile("cp.async.wait_group 0;" ::: "memory")
#define CP_WAIT1()  asm volatile("cp.async.wait_group 1;" ::: "memory")

// smem tile layouts (row-major, padded for conflict-free fragment LDS)
#define AST 20                     // A chunk: [128][20] floats
#define WST 20                     // W chunk (NT): [64][20]
#define VST 72                     // V chunk (NN): [16][72]
#define ABYTES (128*AST*4)         // 10240
#define WBYTES (64*WST*4)          // 5120
#define VBYTES (16*VST*4)          // 4608

// A chunk: 128 rows x 16 floats = 512 segs of 16B; 256 threads x2
__device__ __forceinline__ void cpA(unsigned dst, const float* __restrict__ Ab,
                                    int lda, int k0, int tid)
{
#pragma unroll
    for (int i = 0; i < 2; i++) {
        int idx = tid + i * 256;
        int row = idx >> 2, j = idx & 3;
        cp16(dst + (row * AST + j * 4) * 4, Ab + (size_t)row * lda + k0 + j * 4);
    }
}
// W NT chunk: 64 rows x 16 = 256 segs
__device__ __forceinline__ void cpW(unsigned dst, const float* __restrict__ Wb,
                                    int ldw, int k0, int tid)
{
    int row = tid >> 2, j = tid & 3;
    cp16(dst + (row * WST + j * 4) * 4, Wb + (size_t)row * ldw + k0 + j * 4);
}
// V NN chunk: 16 rows x 64 = 256 segs
__device__ __forceinline__ void cpV(unsigned dst, const float* __restrict__ Vb,
                                    int ldv, int k0, int tid)
{
    int row = tid >> 4, j = tid & 15;
    cp16(dst + (row * VST + j * 4) * 4, Vb + (size_t)(k0 + row) * ldv + j * 4);
}

// ---------------- mma cores ----------------
__device__ __forceinline__ void mma8(float* c, const unsigned* a, const unsigned* b) {
    asm volatile(
        "mma.sync.aligned.m16n8k8.row.col.f32.tf32.tf32.f32 "
        "{%0,%1,%2,%3}, {%4,%5,%6,%7}, {%8,%9}, {%0,%1,%2,%3};"
        : "+f"(c[0]), "+f"(c[1]), "+f"(c[2]), "+f"(c[3])
        : "r"(a[0]), "r"(a[1]), "r"(a[2]), "r"(a[3]), "r"(b[0]), "r"(b[1]));
}

// NT: A[m][k] in [128][AST], W[n][k] in [64][WST]
__device__ __forceinline__ void mma_chunk_nt(
    const float* __restrict__ As, const float* __restrict__ Ws,
    int warp_m, int warp_n, int lane, float c[2][4][4])
{
    int r = lane >> 2, q = lane & 3;
    const float* Ap = As + (warp_m + r) * AST + q;
    const float* Bp = Ws + (warp_n + r) * WST + q;
#pragma unroll
    for (int ks = 0; ks < 2; ks++) {
        int kb = ks * 8;
        unsigned a[2][4], b[4][2];
#pragma unroll
        for (int mf = 0; mf < 2; mf++) {
            const float* p = Ap + mf * 16 * AST + kb;
            a[mf][0] = __float_as_uint(p[0]);
            a[mf][1] = __float_as_uint(p[8 * AST]);
            a[mf][2] = __float_as_uint(p[4]);
            a[mf][3] = __float_as_uint(p[8 * AST + 4]);
        }
#pragma unroll
        for (int nf = 0; nf < 4; nf++) {
            const float* p = Bp + nf * 8 * WST + kb;
            b[nf][0] = __float_as_uint(p[0]);
            b[nf][1] = __float_as_uint(p[4]);
        }
#pragma unroll
        for (int mf = 0; mf < 2; mf++)
#pragma unroll
            for (int nf = 0; nf < 4; nf++)
                mma8(c[mf][nf], a[mf], b[nf]);
    }
}

// NN: A as above, V[k][n] in [16][VST]
__device__ __forceinline__ void mma_chunk_nn(
    const float* __restrict__ As, const float* __restrict__ Vs,
    int warp_m, int warp_n, int lane, float c[2][4][4])
{
    int r = lane >> 2, q = lane & 3;
    const float* Ap = As + (warp_m + r) * AST + q;
    const float* Bp = Vs + q * VST + warp_n + r;
#pragma unroll
    for (int ks = 0; ks < 2; ks++) {
        int kb = ks * 8;
        unsigned a[2][4], b[4][2];
#pragma unroll
        for (int mf = 0; mf < 2; mf++) {
            const float* p = Ap + mf * 16 * AST + kb;
            a[mf][0] = __float_as_uint(p[0]);
            a[mf][1] = __float_as_uint(p[8 * AST]);
            a[mf][2] = __float_as_uint(p[4]);
            a[mf][3] = __float_as_uint(p[8 * AST + 4]);
        }
#pragma unroll
        for (int nf = 0; nf < 4; nf++) {
            b[nf][0] = __float_as_uint(Bp[kb * VST + nf * 8]);
            b[nf][1] = __float_as_uint(Bp[kb * VST + 4 * VST + nf * 8]);
        }
#pragma unroll
        for (int mf = 0; mf < 2; mf++)
#pragma unroll
            for (int nf = 0; nf < 4; nf++)
                mma8(c[mf][nf], a[mf], b[nf]);
    }
}

// ---------------- generic dense NT GEMM (3-stage cp.async pipeline) ----------------
__global__ __launch_bounds__(256) void gemm_nt(
    const float* __restrict__ A, int lda,
    const float* __restrict__ W, int ldw,
    const float* __restrict__ bias,
    const float* __restrict__ res,
    float* __restrict__ C, int ldc,
    int K, int relu, int cvtOut)
{
    __shared__ float As[3][128 * AST];
    __shared__ float Ws[3][64 * WST];
    int tid = threadIdx.x, w = tid >> 5, lane = tid & 31;
    int warp_m = (w >> 1) * 32, warp_n = (w & 1) * 32;
    int row0 = blockIdx.y * 128, col0 = blockIdx.x * 64;
    const float* Ab = A + (size_t)row0 * lda;
    const float* Wb = W + (size_t)col0 * ldw;
    unsigned sA = (unsigned)__cvta_generic_to_shared(As);
    unsigned sW = (unsigned)__cvta_generic_to_shared(Ws);
    float c[2][4][4] = {};
    int nch = K >> 4;      // always >= 4 here
#pragma unroll
    for (int s = 0; s < 2; s++) {
        cpA(sA + s * ABYTES, Ab, lda, s << 4, tid);
        cpW(sW + s * WBYTES, Wb, ldw, s << 4, tid);
        CP_COMMIT();
    }
    for (int ch = 0; ch < nch; ch++) {
        CP_WAIT1();
        __syncthreads();
        int nx = ch + 2;
        if (nx < nch) {
            int bs = nx % 3;
            cpA(sA + bs * ABYTES, Ab, lda, nx << 4, tid);
            cpW(sW + bs * WBYTES, Wb, ldw, nx << 4, tid);
            CP_COMMIT();
        }
        mma_chunk_nt(As[ch % 3], Ws[ch % 3], warp_m, warp_n, lane, c);
    }
    int r = lane >> 2, q = lane & 3;
#pragma unroll
    for (int mf = 0; mf < 2; mf++)
#pragma unroll
    for (int rr = 0; rr < 2; rr++) {
        int row = row0 + warp_m + mf * 16 + r + rr * 8;
#pragma unroll
        for (int nf = 0; nf < 4; nf++) {
            int col = col0 + warp_n + nf * 8 + 2 * q;
            float2 o = make_float2(c[mf][nf][2 * rr], c[mf][nf][2 * rr + 1]);
            if (bias) { float2 bb = *(const float2*)(bias + col); o.x += bb.x; o.y += bb.y; }
            if (res) {
                float2 rv = *(const float2*)(res + (size_t)row * ldc + col);
                o.x += rv.x; o.y += rv.y;
            }
            if (relu) { o.x = fmaxf(o.x, 0.f); o.y = fmaxf(o.y, 0.f); }
            if (cvtOut) { o.x = cvt(o.x); o.y = cvt(o.y); }
            *(float2*)(C + (size_t)row * ldc + col) = o;
        }
    }
}

// ---------------- ql[l,b,t,h*64+e] = q[b,t,h*64+:] @ rel[l]^T (rounded out) ----------------
__global__ __launch_bounds__(256) void ql_kernel(
    const float* __restrict__ qm, const float* __restrict__ rel, float* __restrict__ qlb)
{
    __shared__ float As[3][128 * AST];
    __shared__ float Ws[3][64 * WST];
    int z = blockIdx.x;                       // l*64 + b*8 + h
    int h = z & 7, b = (z >> 3) & 7, l = z >> 6;
    int i0 = blockIdx.y * 128;
    int tid = threadIdx.x, w = tid >> 5, lane = tid & 31;
    int warp_m = (w >> 1) * 32, warp_n = (w & 1) * 32;
    const float* Ab = qm + (size_t)(b * T_ + i0) * D_ + h * HD_;
    const float* Wb = rel + (size_t)l * HD_ * HD_;
    unsigned sA = (unsigned)__cvta_generic_to_shared(As);
    unsigned sW = (unsigned)__cvta_generic_to_shared(Ws);
    float c[2][4][4] = {};
    const int nch = HD_ / 16;   // 4
#pragma unroll
    for (int s = 0; s < 2; s++) {
        cpA(sA + s * ABYTES, Ab, D_, s << 4, tid);
        cpW(sW + s * WBYTES, Wb, HD_, s << 4, tid);
        CP_COMMIT();
    }
    for (int ch = 0; ch < nch; ch++) {
        CP_WAIT1();
        __syncthreads();
        int nx = ch + 2;
        if (nx < nch) {
            int bs = nx % 3;
            cpA(sA + bs * ABYTES, Ab, D_, nx << 4, tid);
            cpW(sW + bs * WBYTES, Wb, HD_, nx << 4, tid);
            CP_COMMIT();
        }
        mma_chunk_nt(As[ch % 3], Ws[ch % 3], warp_m, warp_n, lane, c);
    }
    int r = lane >> 2, q = lane & 3;
    float* Ob = qlb + (size_t)((l * B_ + b) * T_ + i0) * D_ + h * HD_;
#pragma unroll
    for (int mf = 0; mf < 2; mf++)
#pragma unroll
    for (int rr = 0; rr < 2; rr++) {
        int row = warp_m + mf * 16 + r + rr * 8;
#pragma unroll
        for (int nf = 0; nf < 4; nf++) {
            int col = warp_n + nf * 8 + 2 * q;
            *(float2*)(Ob + (size_t)row * D_ + col) =
                make_float2(cvt(c[mf][nf][2 * rr]), cvt(c[mf][nf][2 * rr + 1]));
        }
    }
}

// ---------------- sa scores: persistent K tile, 2-stage A ring over 32 (l,kc) chunks ----------------
__global__ __launch_bounds__(256) void sa_scores_kernel(
    const float* __restrict__ qlb, const float* __restrict__ km,
    const float* __restrict__ em, const unsigned char* __restrict__ pad,
    float* __restrict__ sc)
{
    __shared__ float As[2][128 * AST];
    __shared__ float Ws4[4][64 * WST];
    int z = blockIdx.z; int h = z & 7, b = z >> 3;
    int i0 = blockIdx.y * 128, j0 = blockIdx.x * 64;
    int tid = threadIdx.x, w = tid >> 5, lane = tid & 31;
    int warp_m = (w >> 1) * 32, warp_n = (w & 1) * 32;
    int r = lane >> 2, q = lane & 3;
    unsigned sA = (unsigned)__cvta_generic_to_shared(As);
    unsigned sW = (unsigned)__cvta_generic_to_shared(Ws4);
    const float* Kb = km + (size_t)(b * T_ + j0) * D_ + h * HD_;
    const float* A0 = qlb + (size_t)(b * T_ + i0) * D_ + h * HD_;   // l stride below
    const size_t LSTR = (size_t)B_ * T_ * D_;
#pragma unroll
    for (int kc = 0; kc < 4; kc++)
        cpW(sW + kc * WBYTES, Kb, D_, kc << 4, tid);
    cpA(sA, A0, D_, 0, tid);
    CP_COMMIT();

    float acc[2][4][4] = {};
    int cc = 0;
    for (int l = 0; l < L_; l++) {
        float c[2][4][4] = {};
#pragma unroll
        for (int kc = 0; kc < 4; kc++) {
            CP_WAIT0();
            __syncthreads();
            bool have_next = !(l == L_ - 1 && kc == 3);
            if (have_next) {
                int nl = (kc == 3) ? l + 1 : l;
                int nk = (kc == 3) ? 0 : kc + 1;
                cpA(sA + ((cc + 1) & 1) * ABYTES, A0 + (size_t)nl * LSTR, D_, nk << 4, tid);
                CP_COMMIT();
            }
            mma_chunk_nt(As[cc & 1], Ws4[kc], warp_m, warp_n, lane, c);
            cc++;
        }
        const float* emb = em + (size_t)(b * L_ + l) * T_ * T_;
#pragma unroll
        for (int mf = 0; mf < 2; mf++)
#pragma unroll
        for (int rr = 0; rr < 2; rr++) {
            int i = i0 + warp_m + mf * 16 + r + rr * 8;
#pragma unroll
            for (int nf = 0; nf < 4; nf++) {
                int j = j0 + warp_n + nf * 8 + 2 * q;
                float2 e = *(const float2*)(emb + (size_t)i * T_ + j);
                acc[mf][nf][2 * rr]     += e.x * c[mf][nf][2 * rr];
                acc[mf][nf][2 * rr + 1] += e.y * c[mf][nf][2 * rr + 1];
            }
        }
    }
#pragma unroll
    for (int mf = 0; mf < 2; mf++)
#pragma unroll
    for (int rr = 0; rr < 2; rr++) {
        int i = i0 + warp_m + mf * 16 + r + rr * 8;
#pragma unroll
        for (int nf = 0; nf < 4; nf++) {
            int j = j0 + warp_n + nf * 8 + 2 * q;
            const unsigned char* pp = pad + (size_t)(b * T_ + i) * T_ + j;
            float2 o;
            o.x = pp[0] ? -1e9f : acc[mf][nf][2 * rr] * 0.125f;
            o.y = pp[1] ? -1e9f : acc[mf][nf][2 * rr + 1] * 0.125f;
            *(float2*)(sc + ((size_t)z * T_ + i) * T_ + j) = o;
        }
    }
}

// ---------------- cross scores: (cq . ck^T) * scale ----------------
__global__ __launch_bounds__(256) void ca_scores_kernel(
    const float* __restrict__ cq, const float* __restrict__ ck, float* __restrict__ sc)
{
    __shared__ float As[3][128 * AST];
    __shared__ float Ws[3][64 * WST];
    int z = blockIdx.z; int h = z & 7, b = z >> 3;
    int i0 = blockIdx.y * 128, j0 = blockIdx.x * 64;
    int tid = threadIdx.x, w = tid >> 5, lane = tid & 31;
    int warp_m = (w >> 1) * 32, warp_n = (w & 1) * 32;
    const float* Ab = cq + (size_t)(b * T_ + i0) * D_ + h * HD_;
    const float* Wb = ck + (size_t)(b * S_ + j0) * D_ + h * HD_;
    unsigned sA = (unsigned)__cvta_generic_to_shared(As);
    unsigned sW = (unsigned)__cvta_generic_to_shared(Ws);
    float c[2][4][4] = {};
    const int nch = HD_ / 16;
#pragma unroll
    for (int s = 0; s < 2; s++) {
        cpA(sA + s * ABYTES, Ab, D_, s << 4, tid);
        cpW(sW + s * WBYTES, Wb, D_, s << 4, tid);
        CP_COMMIT();
    }
    for (int ch = 0; ch < nch; ch++) {
        CP_WAIT1();
        __syncthreads();
        int nx = ch + 2;
        if (nx < nch) {
            int bs = nx % 3;
            cpA(sA + bs * ABYTES, Ab, D_, nx << 4, tid);
            cpW(sW + bs * WBYTES, Wb, D_, nx << 4, tid);
            CP_COMMIT();
        }
        mma_chunk_nt(As[ch % 3], Ws[ch % 3], warp_m, warp_n, lane, c);
    }
    int r = lane >> 2, q = lane & 3;
#pragma unroll
    for (int mf = 0; mf < 2; mf++)
#pragma unroll
    for (int rr = 0; rr < 2; rr++) {
        int i = i0 + warp_m + mf * 16 + r + rr * 8;
#pragma unroll
        for (int nf = 0; nf < 4; nf++) {
            int j = j0 + warp_n + nf * 8 + 2 * q;
            *(float2*)(sc + ((size_t)z * T_ + i) * S_ + j) =
                make_float2(c[mf][nf][2 * rr] * 0.125f, c[mf][nf][2 * rr + 1] * 0.125f);
        }
    }
}

// ---------------- row softmax over width 512 (rounded output) ----------------
__global__ void softmax_kernel(float* __restrict__ sc)
{
    __shared__ float red[8];
    int row = blockIdx.x;
    int tid = threadIdx.x;
    float* p = sc + (size_t)row * 512;
    float a0 = p[tid], a1 = p[tid + 256];
    float m = fmaxf(a0, a1);
#pragma unroll
    for (int o = 16; o; o >>= 1) m = fmaxf(m, __shfl_xor_sync(0xffffffffu, m, o));
    if ((tid & 31) == 0) red[tid >> 5] = m;
    __syncthreads();
    m = red[0];
#pragma unroll
    for (int i = 1; i < 8; i++) m = fmaxf(m, red[i]);
    float e0 = __expf(a0 - m), e1 = __expf(a1 - m);
    float s = e0 + e1;
#pragma unroll
    for (int o = 16; o; o >>= 1) s += __shfl_xor_sync(0xffffffffu, s, o);
    __syncthreads();
    if ((tid & 31) == 0) red[tid >> 5] = s;
    __syncthreads();
    s = red[0] + red[1] + red[2] + red[3] + red[4] + red[5] + red[6] + red[7];
    float inv = 1.0f / s;
    p[tid] = cvt(e0 * inv);
    p[tid + 256] = cvt(e1 * inv);
}

// ---------------- o = attn @ v (NN, rounded out) ----------------
__global__ __launch_bounds__(256) void attn_v_kernel(
    const float* __restrict__ attn, const float* __restrict__ vm,
    float* __restrict__ o, int kdim)
{
    __shared__ float As[3][128 * AST];
    __shared__ float Vs[3][16 * VST];
    int z = blockIdx.z; int h = z & 7, b = z >> 3;
    int i0 = blockIdx.y * 128;
    int tid = threadIdx.x, w = tid >> 5, lane = tid & 31;
    int warp_m = (w >> 1) * 32, warp_n = (w & 1) * 32;
    const float* Ab = attn + (size_t)z * T_ * kdim + (size_t)i0 * kdim;
    const float* Vb = vm + (size_t)b * kdim * D_ + h * HD_;
    unsigned sA = (unsigned)__cvta_generic_to_shared(As);
    unsigned sV = (unsigned)__cvta_generic_to_shared(Vs);
    float c[2][4][4] = {};
    int nch = kdim >> 4;
#pragma unroll
    for (int s = 0; s < 2; s++) {
        cpA(sA + s * ABYTES, Ab, kdim, s << 4, tid);
        cpV(sV + s * VBYTES, Vb, D_, s << 4, tid);
        CP_COMMIT();
    }
    for (int ch = 0; ch < nch; ch++) {
        CP_WAIT1();
        __syncthreads();
        int nx = ch + 2;
        if (nx < nch) {
            int bs = nx % 3;
            cpA(sA + bs * ABYTES, Ab, kdim, nx << 4, tid);
            cpV(sV + bs * VBYTES, Vb, D_, nx << 4, tid);
            CP_COMMIT();
        }
        mma_chunk_nn(As[ch % 3], Vs[ch % 3], warp_m, warp_n, lane, c);
    }
    int r = lane >> 2, q = lane & 3;
    float* Ob = o + (size_t)(b * T_ + i0) * D_ + h * HD_;
#pragma unroll
    for (int mf = 0; mf < 2; mf++)
#pragma unroll
    for (int rr = 0; rr < 2; rr++) {
        int row = warp_m + mf * 16 + r + rr * 8;
#pragma unroll
        for (int nf = 0; nf < 4; nf++) {
            int col = warp_n + nf * 8 + 2 * q;
            *(float2*)(Ob + (size_t)row * D_ + col) =
                make_float2(cvt(c[mf][nf][2 * rr]), cvt(c[mf][nf][2 * rr + 1]));
        }
    }
}

// ---------------- (T,B,D) -> (B,T,D) gather; raw (optional) + rounded outputs ----------------
__global__ void transpose_tb(const float* __restrict__ in, float* __restrict__ out_raw,
                             float* __restrict__ out_cvt, int Tdim)
{
    int row = blockIdx.x;
    int t = row / B_, b = row - t * B_;
    float4 v = ((const float4*)(in + (size_t)(t * B_ + b) * D_))[threadIdx.x];
    size_t off = (size_t)(b * Tdim + t) * D_;
    if (out_raw) ((float4*)(out_raw + off))[threadIdx.x] = v;
    float4 o = make_float4(cvt(v.x), cvt(v.y), cvt(v.z), cvt(v.w));
    ((float4*)(out_cvt + off))[threadIdx.x] = o;
}

// ---------------- LayerNorm over D=512; raw + optional rounded outputs ----------------
__global__ void ln_kernel(const float* __restrict__ in, const float* __restrict__ sg,
                          const float* __restrict__ bg, float* __restrict__ out,
                          float* __restrict__ out_cvt, int transpose)
{
    __shared__ float red[4];
    int row = blockIdx.x;
    int tid = threadIdx.x;
    const float* x = in + (size_t)row * D_;
    float v[4];
#pragma unroll
    for (int i = 0; i < 4; i++) v[i] = x[tid + i * 128];
    float s = v[0] + v[1] + v[2] + v[3];
#pragma unroll
    for (int o = 16; o; o >>= 1) s += __shfl_xor_sync(0xffffffffu, s, o);
    if ((tid & 31) == 0) red[tid >> 5] = s;
    __syncthreads();
    float mean = (red[0] + red[1] + red[2] + red[3]) * (1.0f / D_);
    __syncthreads();
    float qv = 0.f;
#pragma unroll
    for (int i = 0; i < 4; i++) { float d = v[i] - mean; qv += d * d; }
#pragma unroll
    for (int o = 16; o; o >>= 1) qv += __shfl_xor_sync(0xffffffffu, qv, o);
    if ((tid & 31) == 0) red[tid >> 5] = qv;
    __syncthreads();
    float var = (red[0] + red[1] + red[2] + red[3]) * (1.0f / D_);
    float inv = rsqrtf(var + 1e-5f);
    int orow = row;
    if (transpose) { int b = row / T_; int t = row - b * T_; orow = t * B_ + b; }
    float* op = out + (size_t)orow * D_;
    float* opc = out_cvt ? out_cvt + (size_t)orow * D_ : nullptr;
#pragma unroll
    for (int i = 0; i < 4; i++) {
        int d = tid + i * 128;
        float val = (v[i] - mean) * inv * sg[d] + bg[d];
        op[d] = val;
        if (opc) opc[d] = cvt(val);
    }
}

// ---------------- weight round-to-tf32 pass ----------------
struct CvtJob { const float* src; float* dst; int n; };
struct CvtParams { CvtJob j[9]; };
__global__ void cvt_weights(CvtParams p)
{
    const CvtJob J = p.j[blockIdx.y];
    int i = (blockIdx.x * 256 + threadIdx.x) * 4;
    if (i < J.n) {
        float4 v = *(const float4*)(J.src + i);
        *(float4*)(J.dst + i) = make_float4(cvt(v.x), cvt(v.y), cvt(v.z), cvt(v.w));
    }
}

// ---------------- launch ----------------
extern "C" void kernel_launch(void* const* d_in, const int* in_sizes, int n_in,
                              void* d_out, int out_size)
{
    const float* tgt       = (const float*)d_in[0];
    const float* em        = (const float*)d_in[1];
    const unsigned char* pad = (const unsigned char*)d_in[2];
    const float* memory    = (const float*)d_in[3];
    const float* sa_q_w    = (const float*)d_in[4];
    const float* sa_q_b    = (const float*)d_in[5];
    const float* sa_k_w    = (const float*)d_in[6];
    const float* sa_k_b    = (const float*)d_in[7];
    const float* sa_v_w    = (const float*)d_in[8];
    const float* sa_v_b    = (const float*)d_in[9];
    const float* sa_rel    = (const float*)d_in[10];
    const float* sa_out_w  = (const float*)d_in[11];
    const float* sa_out_b  = (const float*)d_in[12];
    const float* ca_in_w   = (const float*)d_in[13];
    const float* ca_in_b   = (const float*)d_in[14];
    const float* ca_out_w  = (const float*)d_in[15];
    const float* ca_out_b  = (const float*)d_in[16];
    const float* lin1_w    = (const float*)d_in[17];
    const float* lin1_b    = (const float*)d_in[18];
    const float* lin2_w    = (const float*)d_in[19];
    const float* lin2_b    = (const float*)d_in[20];
    const float* ln1_s     = (const float*)d_in[21];
    const float* ln1_b     = (const float*)d_in[22];
    const float* ln2_s     = (const float*)d_in[23];
    const float* ln2_b     = (const float*)d_in[24];
    const float* ln3_s     = (const float*)d_in[25];
    const float* ln3_b     = (const float*)d_in[26];

    float *x, *xc, *memc, *q, *k, *v, *ql, *sc, *o, *tmp, *x1, *x1c, *x2, *x2c, *ffn, *wts;
    cudaGetSymbolAddress((void**)&x,    g_x);
    cudaGetSymbolAddress((void**)&xc,   g_xc);
    cudaGetSymbolAddress((void**)&memc, g_memc);
    cudaGetSymbolAddress((void**)&q,    g_q);
    cudaGetSymbolAddress((void**)&k,    g_k);
    cudaGetSymbolAddress((void**)&v,    g_v);
    cudaGetSymbolAddress((void**)&ql,   g_ql);
    cudaGetSymbolAddress((void**)&sc,   g_sc);
    cudaGetSymbolAddress((void**)&o,    g_o);
    cudaGetSymbolAddress((void**)&tmp,  g_tmp);
    cudaGetSymbolAddress((void**)&x1,   g_x1);
    cudaGetSymbolAddress((void**)&x1c,  g_x1c);
    cudaGetSymbolAddress((void**)&x2,   g_x2);
    cudaGetSymbolAddress((void**)&x2c,  g_x2c);
    cudaGetSymbolAddress((void**)&ffn,  g_ffn);
    cudaGetSymbolAddress((void**)&wts,  g_wts);

    // weight rounding pass
    CvtParams cp;
    cp.j[0] = { sa_q_w,   wts + WQ_OFF,   D_ * D_ };
    cp.j[1] = { sa_k_w,   wts + WK_OFF,   D_ * D_ };
    cp.j[2] = { sa_v_w,   wts + WV_OFF,   D_ * D_ };
    cp.j[3] = { sa_out_w, wts + WO_OFF,   D_ * D_ };
    cp.j[4] = { ca_in_w,  wts + WCA_OFF,  3 * D_ * D_ };
    cp.j[5] = { ca_out_w, wts + WCAO_OFF, D_ * D_ };
    cp.j[6] = { lin1_w,   wts + WL1_OFF,  F_ * D_ };
    cp.j[7] = { lin2_w,   wts + WL2_OFF,  D_ * F_ };
    cp.j[8] = { sa_rel,   wts + WREL_OFF, L_ * HD_ * HD_ };
    cvt_weights<<<dim3(1024, 9), 256>>>(cp);

    const dim3 gproj(D_ / 64, (B_ * T_) / 128);       // (8, 32)
    const dim3 gattn(T_ / 64, T_ / 128, B_ * H_);     // (8, 4, 64)
    const dim3 gav(1, T_ / 128, B_ * H_);             // (1, 4, 64)

    // --- self-attention ---
    transpose_tb<<<T_ * B_, 128>>>(tgt, x, xc, T_);
    transpose_tb<<<S_ * B_, 128>>>(memory, nullptr, memc, S_);
    gemm_nt<<<gproj, 256>>>(xc, D_, wts + WQ_OFF, D_, sa_q_b, nullptr, q, D_, D_, 0, 1);
    gemm_nt<<<gproj, 256>>>(xc, D_, wts + WK_OFF, D_, sa_k_b, nullptr, k, D_, D_, 0, 1);
    gemm_nt<<<gproj, 256>>>(xc, D_, wts + WV_OFF, D_, sa_v_b, nullptr, v, D_, D_, 0, 1);
    ql_kernel<<<dim3(L_ * B_ * H_, T_ / 128), 256>>>(q, wts + WREL_OFF, ql);
    sa_scores_kernel<<<gattn, 256>>>(ql, k, em, pad, sc);
    softmax_kernel<<<B_ * H_ * T_, 256>>>(sc);
    attn_v_kernel<<<gav, 256>>>(sc, v, o, T_);
    gemm_nt<<<gproj, 256>>>(o, D_, wts + WO_OFF, D_, sa_out_b, x, tmp, D_, D_, 0, 0);
    ln_kernel<<<B_ * T_, 128>>>(tmp, ln1_s, ln1_b, x1, x1c, 0);

    // --- cross-attention ---
    gemm_nt<<<gproj, 256>>>(x1c,  D_, wts + WCA_OFF,              D_, ca_in_b,          nullptr, q, D_, D_, 0, 1);
    gemm_nt<<<gproj, 256>>>(memc, D_, wts + WCA_OFF + D_ * D_,    D_, ca_in_b + D_,     nullptr, k, D_, D_, 0, 1);
    gemm_nt<<<gproj, 256>>>(memc, D_, wts + WCA_OFF + 2 * D_ * D_, D_, ca_in_b + 2 * D_, nullptr, v, D_, D_, 0, 1);
    ca_scores_kernel<<<dim3(S_ / 64, T_ / 128, B_ * H_), 256>>>(q, k, sc);
    softmax_kernel<<<B_ * H_ * T_, 256>>>(sc);
    attn_v_kernel<<<gav, 256>>>(sc, v, o, S_);
    gemm_nt<<<gproj, 256>>>(o, D_, wts + WCAO_OFF, D_, ca_out_b, x1, tmp, D_, D_, 0, 0);
    ln_kernel<<<B_ * T_, 128>>>(tmp, ln2_s, ln2_b, x2, x2c, 0);

    // --- FFN ---
    gemm_nt<<<dim3(F_ / 64, (B_ * T_) / 128), 256>>>(x2c, D_, wts + WL1_OFF, D_, lin1_b, nullptr, ffn, F_, D_, 1, 1);
    gemm_nt<<<gproj, 256>>>(ffn, F_, wts + WL2_OFF, F_, lin2_b, x2, tmp, D_, F_, 0, 0);
    ln_kernel<<<B_ * T_, 128>>>(tmp, ln3_s, ln3_b, (float*)d_out, nullptr, 1);
}

// round 10
// speedup vs baseline: 2.4321x; 1.0458x over previous
#include <cuda_runtime.h>

#define T_ 512
#define S_ 512
#define B_ 8
#define D_ 512
#define H_ 8
#define HD_ 64
#define L_ 8
#define F_ 2048

// ---------------- scratch (device globals; no runtime allocation) ----------------
__device__ float g_x  [B_*T_*D_];     // raw (B,T,D) tgt  (residual use)
__device__ float g_xc [B_*T_*D_];     // tf32-rounded copy (GEMM input)
__device__ float g_memc[B_*S_*D_];    // rounded memory (B,S,D)
__device__ float g_q  [B_*T_*D_];
__device__ float g_k  [B_*S_*D_];
__device__ float g_v  [B_*S_*D_];
__device__ float g_ql [L_*B_*T_*D_];
__device__ float g_sc [B_*H_*T_*T_];
__device__ float g_o  [B_*T_*D_];
__device__ float g_tmp[B_*T_*D_];
__device__ float g_x1 [B_*T_*D_];
__device__ float g_x1c[B_*T_*D_];
__device__ float g_x2 [B_*T_*D_];
__device__ float g_x2c[B_*T_*D_];
__device__ float g_ffn[B_*T_*F_];
__device__ float g_wts[4227072];

#define WQ_OFF   0
#define WK_OFF   262144
#define WV_OFF   524288
#define WO_OFF   786432
#define WCA_OFF  1048576
#define WCAO_OFF 1835008
#define WL1_OFF  2097152
#define WL2_OFF  3145728
#define WREL_OFF 4194304

__device__ __forceinline__ float cvt(float f) {
    unsigned r; asm("cvt.rna.tf32.f32 %0, %1;" : "=r"(r) : "f"(f));
    return __uint_as_float(r);
}
__device__ __forceinline__ unsigned fu(float f) { return __float_as_uint(f); }

// ---------------- cp.async helpers ----------------
__device__ __forceinline__ void cp16(unsigned dst, const void* src) {
    asm volatile("cp.async.ca.shared.global [%0], [%1], 16;" :: "r"(dst), "l"(src));
}
#define CP_COMMIT() asm volatile("cp.async.commit_group;" ::: "memory")
#define CP_WAIT0()  asm volatile("cp.async.wait_group 0;" ::: "memory")
#define CP_WAIT1()  asm volatile("cp.async.wait_group 1;" ::: "memory")

// smem tile layouts (row-major; pads verified conflict-free for float2 frag loads)
#define AST 24                     // A chunk: [128][24] floats
#define WST 24                     // W chunk (NT): [64][24]
#define VST 68                     // V chunk (NN): [16][68]
#define ABYTES (128*AST*4)         // 12288
#define WBYTES (64*WST*4)          // 6144
#define VBYTES (16*VST*4)          // 4352
#define SM_GEMM (3*(ABYTES+WBYTES))   // 55296
#define SM_SA   (2*ABYTES+4*WBYTES)   // 49152
#define SM_AV   (3*(ABYTES+VBYTES))   // 49920

__device__ __forceinline__ void cpA(unsigned dst, const float* __restrict__ Ab,
                                    int lda, int k0, int tid)
{
#pragma unroll
    for (int i = 0; i < 2; i++) {
        int idx = tid + i * 256;
        int row = idx >> 2, j = idx & 3;
        cp16(dst + (row * AST + j * 4) * 4, Ab + (size_t)row * lda + k0 + j * 4);
    }
}
__device__ __forceinline__ void cpW(unsigned dst, const float* __restrict__ Wb,
                                    int ldw, int k0, int tid)
{
    int row = tid >> 2, j = tid & 3;
    cp16(dst + (row * WST + j * 4) * 4, Wb + (size_t)row * ldw + k0 + j * 4);
}
__device__ __forceinline__ void cpV(unsigned dst, const float* __restrict__ Vb,
                                    int ldv, int k0, int tid)
{
    int row = tid >> 4, j = tid & 15;
    cp16(dst + (row * VST + j * 4) * 4, Vb + (size_t)(k0 + row) * ldv + j * 4);
}

// ---------------- mma cores ----------------
__device__ __forceinline__ void mma8(float* c, const unsigned* a, const unsigned* b) {
    asm volatile(
        "mma.sync.aligned.m16n8k8.row.col.f32.tf32.tf32.f32 "
        "{%0,%1,%2,%3}, {%4,%5,%6,%7}, {%8,%9}, {%0,%1,%2,%3};"
        : "+f"(c[0]), "+f"(c[1]), "+f"(c[2]), "+f"(c[3])
        : "r"(a[0]), "r"(a[1]), "r"(a[2]), "r"(a[3]), "r"(b[0]), "r"(b[1]));
}

// k-permuted fragments: hw k-lane q covers logical k = 2q (a0/a2... no: a0,b0) and 2q+1
// (a2,b1); adjacent floats -> LDS.64. Same permutation on A and B => exact same dot product.
__device__ __forceinline__ void mma_chunk_nt(
    const float* __restrict__ As, const float* __restrict__ Ws,
    int warp_m, int warp_n, int lane, float c[2][4][4])
{
    int r = lane >> 2, q = lane & 3;
    const float* Ap = As + (warp_m + r) * AST + 2 * q;
    const float* Bp = Ws + (warp_n + r) * WST + 2 * q;
#pragma unroll
    for (int ks = 0; ks < 2; ks++) {
        int kb = ks * 8;
        float2 aL[2][2];
#pragma unroll
        for (int mf = 0; mf < 2; mf++) {
            aL[mf][0] = *(const float2*)(Ap + (mf * 16) * AST + kb);
            aL[mf][1] = *(const float2*)(Ap + (mf * 16 + 8) * AST + kb);
        }
        float2 bL[4];
#pragma unroll
        for (int nf = 0; nf < 4; nf++)
            bL[nf] = *(const float2*)(Bp + nf * 8 * WST + kb);
#pragma unroll
        for (int mf = 0; mf < 2; mf++) {
            unsigned a[4] = { fu(aL[mf][0].x), fu(aL[mf][1].x),
                              fu(aL[mf][0].y), fu(aL[mf][1].y) };
#pragma unroll
            for (int nf = 0; nf < 4; nf++) {
                unsigned b[2] = { fu(bL[nf].x), fu(bL[nf].y) };
                mma8(c[mf][nf], a, b);
            }
        }
    }
}

__device__ __forceinline__ void mma_chunk_nn(
    const float* __restrict__ As, const float* __restrict__ Vs,
    int warp_m, int warp_n, int lane, float c[2][4][4])
{
    int r = lane >> 2, q = lane & 3;
    const float* Ap = As + (warp_m + r) * AST + 2 * q;
    const float* Bp = Vs + warp_n + r;
#pragma unroll
    for (int ks = 0; ks < 2; ks++) {
        int kb = ks * 8;
        float2 aL[2][2];
#pragma unroll
        for (int mf = 0; mf < 2; mf++) {
            aL[mf][0] = *(const float2*)(Ap + (mf * 16) * AST + kb);
            aL[mf][1] = *(const float2*)(Ap + (mf * 16 + 8) * AST + kb);
        }
#pragma unroll
        for (int mf = 0; mf < 2; mf++) {
            unsigned a[4] = { fu(aL[mf][0].x), fu(aL[mf][1].x),
                              fu(aL[mf][0].y), fu(aL[mf][1].y) };
#pragma unroll
            for (int nf = 0; nf < 4; nf++) {
                unsigned b[2] = { fu(Bp[(kb + 2 * q) * VST + nf * 8]),
                                  fu(Bp[(kb + 2 * q + 1) * VST + nf * 8]) };
                mma8(c[mf][nf], a, b);
            }
        }
    }
}

// ---------------- batched dense NT GEMM (3-stage cp.async, up to 3 jobs via z) ----------------
struct GJob { const float* A; const float* W; const float* bias; const float* res; float* C; };
struct GParams { GJob j[3]; int lda, ldw, ldc, K, relu, cvtOut; };

__global__ __launch_bounds__(256) void gemm_nt(GParams g)
{
    extern __shared__ float smem[];
    float* As = smem;
    float* Ws = smem + 3 * 128 * AST;
    const GJob J = g.j[blockIdx.z];
    int tid = threadIdx.x, w = tid >> 5, lane = tid & 31;
    int warp_m = (w >> 1) * 32, warp_n = (w & 1) * 32;
    int row0 = blockIdx.y * 128, col0 = blockIdx.x * 64;
    const float* Ab = J.A + (size_t)row0 * g.lda;
    const float* Wb = J.W + (size_t)col0 * g.ldw;
    unsigned sA = (unsigned)__cvta_generic_to_shared(As);
    unsigned sW = (unsigned)__cvta_generic_to_shared(Ws);
    float c[2][4][4] = {};
    int nch = g.K >> 4;
#pragma unroll
    for (int s = 0; s < 2; s++) {
        cpA(sA + s * ABYTES, Ab, g.lda, s << 4, tid);
        cpW(sW + s * WBYTES, Wb, g.ldw, s << 4, tid);
        CP_COMMIT();
    }
    for (int ch = 0; ch < nch; ch++) {
        CP_WAIT1();
        __syncthreads();
        int nx = ch + 2;
        if (nx < nch) {
            int bs = nx % 3;
            cpA(sA + bs * ABYTES, Ab, g.lda, nx << 4, tid);
            cpW(sW + bs * WBYTES, Wb, g.ldw, nx << 4, tid);
            CP_COMMIT();
        }
        mma_chunk_nt(As + (ch % 3) * 128 * AST, Ws + (ch % 3) * 64 * WST,
                     warp_m, warp_n, lane, c);
    }
    int r = lane >> 2, q = lane & 3;
#pragma unroll
    for (int mf = 0; mf < 2; mf++)
#pragma unroll
    for (int rr = 0; rr < 2; rr++) {
        int row = row0 + warp_m + mf * 16 + r + rr * 8;
#pragma unroll
        for (int nf = 0; nf < 4; nf++) {
            int col = col0 + warp_n + nf * 8 + 2 * q;
            float2 o = make_float2(c[mf][nf][2 * rr], c[mf][nf][2 * rr + 1]);
            if (J.bias) { float2 bb = *(const float2*)(J.bias + col); o.x += bb.x; o.y += bb.y; }
            if (J.res) {
                float2 rv = *(const float2*)(J.res + (size_t)row * g.ldc + col);
                o.x += rv.x; o.y += rv.y;
            }
            if (g.relu) { o.x = fmaxf(o.x, 0.f); o.y = fmaxf(o.y, 0.f); }
            if (g.cvtOut) { o.x = cvt(o.x); o.y = cvt(o.y); }
            *(float2*)(J.C + (size_t)row * g.ldc + col) = o;
        }
    }
}

// ---------------- ql[l,b,t,h*64+e] = q[b,t,h*64+:] @ rel[l]^T (rounded out) ----------------
__global__ __launch_bounds__(256) void ql_kernel(
    const float* __restrict__ qm, const float* __restrict__ rel, float* __restrict__ qlb)
{
    extern __shared__ float smem[];
    float* As = smem;
    float* Ws = smem + 3 * 128 * AST;
    int z = blockIdx.x;                       // l*64 + b*8 + h
    int h = z & 7, b = (z >> 3) & 7, l = z >> 6;
    int i0 = blockIdx.y * 128;
    int tid = threadIdx.x, w = tid >> 5, lane = tid & 31;
    int warp_m = (w >> 1) * 32, warp_n = (w & 1) * 32;
    const float* Ab = qm + (size_t)(b * T_ + i0) * D_ + h * HD_;
    const float* Wb = rel + (size_t)l * HD_ * HD_;
    unsigned sA = (unsigned)__cvta_generic_to_shared(As);
    unsigned sW = (unsigned)__cvta_generic_to_shared(Ws);
    float c[2][4][4] = {};
    const int nch = HD_ / 16;
#pragma unroll
    for (int s = 0; s < 2; s++) {
        cpA(sA + s * ABYTES, Ab, D_, s << 4, tid);
        cpW(sW + s * WBYTES, Wb, HD_, s << 4, tid);
        CP_COMMIT();
    }
    for (int ch = 0; ch < nch; ch++) {
        CP_WAIT1();
        __syncthreads();
        int nx = ch + 2;
        if (nx < nch) {
            int bs = nx % 3;
            cpA(sA + bs * ABYTES, Ab, D_, nx << 4, tid);
            cpW(sW + bs * WBYTES, Wb, HD_, nx << 4, tid);
            CP_COMMIT();
        }
        mma_chunk_nt(As + (ch % 3) * 128 * AST, Ws + (ch % 3) * 64 * WST,
                     warp_m, warp_n, lane, c);
    }
    int r = lane >> 2, q = lane & 3;
    float* Ob = qlb + (size_t)((l * B_ + b) * T_ + i0) * D_ + h * HD_;
#pragma unroll
    for (int mf = 0; mf < 2; mf++)
#pragma unroll
    for (int rr = 0; rr < 2; rr++) {
        int row = warp_m + mf * 16 + r + rr * 8;
#pragma unroll
        for (int nf = 0; nf < 4; nf++) {
            int col = warp_n + nf * 8 + 2 * q;
            *(float2*)(Ob + (size_t)row * D_ + col) =
                make_float2(cvt(c[mf][nf][2 * rr]), cvt(c[mf][nf][2 * rr + 1]));
        }
    }
}

// ---------------- sa scores: persistent K tile, 2-stage A ring over 32 (l,kc) chunks ----------------
__global__ __launch_bounds__(256) void sa_scores_kernel(
    const float* __restrict__ qlb, const float* __restrict__ km,
    const float* __restrict__ em, const unsigned char* __restrict__ pad,
    float* __restrict__ sc)
{
    extern __shared__ float smem[];
    float* As = smem;
    float* Ws4 = smem + 2 * 128 * AST;
    int z = blockIdx.z; int h = z & 7, b = z >> 3;
    int i0 = blockIdx.y * 128, j0 = blockIdx.x * 64;
    int tid = threadIdx.x, w = tid >> 5, lane = tid & 31;
    int warp_m = (w >> 1) * 32, warp_n = (w & 1) * 32;
    int r = lane >> 2, q = lane & 3;
    unsigned sA = (unsigned)__cvta_generic_to_shared(As);
    unsigned sW = (unsigned)__cvta_generic_to_shared(Ws4);
    const float* Kb = km + (size_t)(b * T_ + j0) * D_ + h * HD_;
    const float* A0 = qlb + (size_t)(b * T_ + i0) * D_ + h * HD_;
    const size_t LSTR = (size_t)B_ * T_ * D_;
#pragma unroll
    for (int kc = 0; kc < 4; kc++)
        cpW(sW + kc * WBYTES, Kb, D_, kc << 4, tid);
    cpA(sA, A0, D_, 0, tid);
    CP_COMMIT();

    float acc[2][4][4] = {};
    int cc = 0;
    for (int l = 0; l < L_; l++) {
        float c[2][4][4] = {};
#pragma unroll
        for (int kc = 0; kc < 4; kc++) {
            CP_WAIT0();
            __syncthreads();
            bool have_next = !(l == L_ - 1 && kc == 3);
            if (have_next) {
                int nl = (kc == 3) ? l + 1 : l;
                int nk = (kc == 3) ? 0 : kc + 1;
                cpA(sA + ((cc + 1) & 1) * ABYTES, A0 + (size_t)nl * LSTR, D_, nk << 4, tid);
                CP_COMMIT();
            }
            mma_chunk_nt(As + (cc & 1) * 128 * AST, Ws4 + kc * 64 * WST,
                         warp_m, warp_n, lane, c);
            cc++;
        }
        const float* emb = em + (size_t)(b * L_ + l) * T_ * T_;
#pragma unroll
        for (int mf = 0; mf < 2; mf++)
#pragma unroll
        for (int rr = 0; rr < 2; rr++) {
            int i = i0 + warp_m + mf * 16 + r + rr * 8;
#pragma unroll
            for (int nf = 0; nf < 4; nf++) {
                int j = j0 + warp_n + nf * 8 + 2 * q;
                float2 e = *(const float2*)(emb + (size_t)i * T_ + j);
                acc[mf][nf][2 * rr]     += e.x * c[mf][nf][2 * rr];
                acc[mf][nf][2 * rr + 1] += e.y * c[mf][nf][2 * rr + 1];
            }
        }
    }
#pragma unroll
    for (int mf = 0; mf < 2; mf++)
#pragma unroll
    for (int rr = 0; rr < 2; rr++) {
        int i = i0 + warp_m + mf * 16 + r + rr * 8;
#pragma unroll
        for (int nf = 0; nf < 4; nf++) {
            int j = j0 + warp_n + nf * 8 + 2 * q;
            const unsigned char* pp = pad + (size_t)(b * T_ + i) * T_ + j;
            float2 o;
            o.x = pp[0] ? -1e9f : acc[mf][nf][2 * rr] * 0.125f;
            o.y = pp[1] ? -1e9f : acc[mf][nf][2 * rr + 1] * 0.125f;
            *(float2*)(sc + ((size_t)z * T_ + i) * T_ + j) = o;
        }
    }
}

// ---------------- cross scores: (cq . ck^T) * scale ----------------
__global__ __launch_bounds__(256) void ca_scores_kernel(
    const float* __restrict__ cq, const float* __restrict__ ck, float* __restrict__ sc)
{
    extern __shared__ float smem[];
    float* As = smem;
    float* Ws = smem + 3 * 128 * AST;
    int z = blockIdx.z; int h = z & 7, b = z >> 3;
    int i0 = blockIdx.y * 128, j0 = blockIdx.x * 64;
    int tid = threadIdx.x, w = tid >> 5, lane = tid & 31;
    int warp_m = (w >> 1) * 32, warp_n = (w & 1) * 32;
    const float* Ab = cq + (size_t)(b * T_ + i0) * D_ + h * HD_;
    const float* Wb = ck + (size_t)(b * S_ + j0) * D_ + h * HD_;
    unsigned sA = (unsigned)__cvta_generic_to_shared(As);
    unsigned sW = (unsigned)__cvta_generic_to_shared(Ws);
    float c[2][4][4] = {};
    const int nch = HD_ / 16;
#pragma unroll
    for (int s = 0; s < 2; s++) {
        cpA(sA + s * ABYTES, Ab, D_, s << 4, tid);
        cpW(sW + s * WBYTES, Wb, D_, s << 4, tid);
        CP_COMMIT();
    }
    for (int ch = 0; ch < nch; ch++) {
        CP_WAIT1();
        __syncthreads();
        int nx = ch + 2;
        if (nx < nch) {
            int bs = nx % 3;
            cpA(sA + bs * ABYTES, Ab, D_, nx << 4, tid);
            cpW(sW + bs * WBYTES, Wb, D_, nx << 4, tid);
            CP_COMMIT();
        }
        mma_chunk_nt(As + (ch % 3) * 128 * AST, Ws + (ch % 3) * 64 * WST,
                     warp_m, warp_n, lane, c);
    }
    int r = lane >> 2, q = lane & 3;
#pragma unroll
    for (int mf = 0; mf < 2; mf++)
#pragma unroll
    for (int rr = 0; rr < 2; rr++) {
        int i = i0 + warp_m + mf * 16 + r + rr * 8;
#pragma unroll
        for (int nf = 0; nf < 4; nf++) {
            int j = j0 + warp_n + nf * 8 + 2 * q;
            *(float2*)(sc + ((size_t)z * T_ + i) * S_ + j) =
                make_float2(c[mf][nf][2 * rr] * 0.125f, c[mf][nf][2 * rr + 1] * 0.125f);
        }
    }
}

// ---------------- row softmax over width 512 (rounded output) ----------------
__global__ void softmax_kernel(float* __restrict__ sc)
{
    __shared__ float red[8];
    int row = blockIdx.x;
    int tid = threadIdx.x;
    float* p = sc + (size_t)row * 512;
    float a0 = p[tid], a1 = p[tid + 256];
    float m = fmaxf(a0, a1);
#pragma unroll
    for (int o = 16; o; o >>= 1) m = fmaxf(m, __shfl_xor_sync(0xffffffffu, m, o));
    if ((tid & 31) == 0) red[tid >> 5] = m;
    __syncthreads();
    m = red[0];
#pragma unroll
    for (int i = 1; i < 8; i++) m = fmaxf(m, red[i]);
    float e0 = __expf(a0 - m), e1 = __expf(a1 - m);
    float s = e0 + e1;
#pragma unroll
    for (int o = 16; o; o >>= 1) s += __shfl_xor_sync(0xffffffffu, s, o);
    __syncthreads();
    if ((tid & 31) == 0) red[tid >> 5] = s;
    __syncthreads();
    s = red[0] + red[1] + red[2] + red[3] + red[4] + red[5] + red[6] + red[7];
    float inv = 1.0f / s;
    p[tid] = cvt(e0 * inv);
    p[tid + 256] = cvt(e1 * inv);
}

// ---------------- o = attn @ v (NN, rounded out) ----------------
__global__ __launch_bounds__(256) void attn_v_kernel(
    const float* __restrict__ attn, const float* __restrict__ vm,
    float* __restrict__ o, int kdim)
{
    extern __shared__ float smem[];
    float* As = smem;
    float* Vs = smem + 3 * 128 * AST;
    int z = blockIdx.z; int h = z & 7, b = z >> 3;
    int i0 = blockIdx.y * 128;
    int tid = threadIdx.x, w = tid >> 5, lane = tid & 31;
    int warp_m = (w >> 1) * 32, warp_n = (w & 1) * 32;
    const float* Ab = attn + (size_t)z * T_ * kdim + (size_t)i0 * kdim;
    const float* Vb = vm + (size_t)b * kdim * D_ + h * HD_;
    unsigned sA = (unsigned)__cvta_generic_to_shared(As);
    unsigned sV = (unsigned)__cvta_generic_to_shared(Vs);
    float c[2][4][4] = {};
    int nch = kdim >> 4;
#pragma unroll
    for (int s = 0; s < 2; s++) {
        cpA(sA + s * ABYTES, Ab, kdim, s << 4, tid);
        cpV(sV + s * VBYTES, Vb, D_, s << 4, tid);
        CP_COMMIT();
    }
    for (int ch = 0; ch < nch; ch++) {
        CP_WAIT1();
        __syncthreads();
        int nx = ch + 2;
        if (nx < nch) {
            int bs = nx % 3;
            cpA(sA + bs * ABYTES, Ab, kdim, nx << 4, tid);
            cpV(sV + bs * VBYTES, Vb, D_, nx << 4, tid);
            CP_COMMIT();
        }
        mma_chunk_nn(As + (ch % 3) * 128 * AST, Vs + (ch % 3) * 16 * VST,
                     warp_m, warp_n, lane, c);
    }
    int r = lane >> 2, q = lane & 3;
    float* Ob = o + (size_t)(b * T_ + i0) * D_ + h * HD_;
#pragma unroll
    for (int mf = 0; mf < 2; mf++)
#pragma unroll
    for (int rr = 0; rr < 2; rr++) {
        int row = warp_m + mf * 16 + r + rr * 8;
#pragma unroll
        for (int nf = 0; nf < 4; nf++) {
            int col = warp_n + nf * 8 + 2 * q;
            *(float2*)(Ob + (size_t)row * D_ + col) =
                make_float2(cvt(c[mf][nf][2 * rr]), cvt(c[mf][nf][2 * rr + 1]));
        }
    }
}

// ---------------- (T,B,D) -> (B,T,D) gather; raw (optional) + rounded outputs ----------------
__global__ void transpose_tb(const float* __restrict__ in, float* __restrict__ out_raw,
                             float* __restrict__ out_cvt, int Tdim)
{
    int row = blockIdx.x;
    int t = row / B_, b = row - t * B_;
    float4 v = ((const float4*)(in + (size_t)(t * B_ + b) * D_))[threadIdx.x];
    size_t off = (size_t)(b * Tdim + t) * D_;
    if (out_raw) ((float4*)(out_raw + off))[threadIdx.x] = v;
    float4 o = make_float4(cvt(v.x), cvt(v.y), cvt(v.z), cvt(v.w));
    ((float4*)(out_cvt + off))[threadIdx.x] = o;
}

// ---------------- LayerNorm over D=512; raw + optional rounded outputs ----------------
__global__ void ln_kernel(const float* __restrict__ in, const float* __restrict__ sg,
                          const float* __restrict__ bg, float* __restrict__ out,
                          float* __restrict__ out_cvt, int transpose)
{
    __shared__ float red[4];
    int row = blockIdx.x;
    int tid = threadIdx.x;
    const float* x = in + (size_t)row * D_;
    float v[4];
#pragma unroll
    for (int i = 0; i < 4; i++) v[i] = x[tid + i * 128];
    float s = v[0] + v[1] + v[2] + v[3];
#pragma unroll
    for (int o = 16; o; o >>= 1) s += __shfl_xor_sync(0xffffffffu, s, o);
    if ((tid & 31) == 0) red[tid >> 5] = s;
    __syncthreads();
    float mean = (red[0] + red[1] + red[2] + red[3]) * (1.0f / D_);
    __syncthreads();
    float qv = 0.f;
#pragma unroll
    for (int i = 0; i < 4; i++) { float d = v[i] - mean; qv += d * d; }
#pragma unroll
    for (int o = 16; o; o >>= 1) qv += __shfl_xor_sync(0xffffffffu, qv, o);
    if ((tid & 31) == 0) red[tid >> 5] = qv;
    __syncthreads();
    float var = (red[0] + red[1] + red[2] + red[3]) * (1.0f / D_);
    float inv = rsqrtf(var + 1e-5f);
    int orow = row;
    if (transpose) { int b = row / T_; int t = row - b * T_; orow = t * B_ + b; }
    float* op = out + (size_t)orow * D_;
    float* opc = out_cvt ? out_cvt + (size_t)orow * D_ : nullptr;
#pragma unroll
    for (int i = 0; i < 4; i++) {
        int d = tid + i * 128;
        float val = (v[i] - mean) * inv * sg[d] + bg[d];
        op[d] = val;
        if (opc) opc[d] = cvt(val);
    }
}

// ---------------- weight round-to-tf32 pass ----------------
struct CvtJob { const float* src; float* dst; int n; };
struct CvtParams { CvtJob j[9]; };
__global__ void cvt_weights(CvtParams p)
{
    const CvtJob J = p.j[blockIdx.y];
    int i = (blockIdx.x * 256 + threadIdx.x) * 4;
    if (i < J.n) {
        float4 v = *(const float4*)(J.src + i);
        *(float4*)(J.dst + i) = make_float4(cvt(v.x), cvt(v.y), cvt(v.z), cvt(v.w));
    }
}

// ---------------- launch ----------------
static GParams mkg(const float* A0, const float* W0, const float* b0, const float* r0, float* C0,
                   const float* A1, const float* W1, const float* b1, float* C1,
                   const float* A2, const float* W2, const float* b2, float* C2,
                   int lda, int ldw, int ldc, int K, int relu, int cvtOut)
{
    GParams g;
    g.j[0] = { A0, W0, b0, r0, C0 };
    g.j[1] = { A1 ? A1 : A0, W1 ? W1 : W0, b1, nullptr, C1 ? C1 : C0 };
    g.j[2] = { A2 ? A2 : A0, W2 ? W2 : W0, b2, nullptr, C2 ? C2 : C0 };
    g.lda = lda; g.ldw = ldw; g.ldc = ldc; g.K = K; g.relu = relu; g.cvtOut = cvtOut;
    return g;
}

extern "C" void kernel_launch(void* const* d_in, const int* in_sizes, int n_in,
                              void* d_out, int out_size)
{
    const float* tgt       = (const float*)d_in[0];
    const float* em        = (const float*)d_in[1];
    const unsigned char* pad = (const unsigned char*)d_in[2];
    const float* memory    = (const float*)d_in[3];
    const float* sa_q_w    = (const float*)d_in[4];
    const float* sa_q_b    = (const float*)d_in[5];
    const float* sa_k_w    = (const float*)d_in[6];
    const float* sa_k_b    = (const float*)d_in[7];
    const float* sa_v_w    = (const float*)d_in[8];
    const float* sa_v_b    = (const float*)d_in[9];
    const float* sa_rel    = (const float*)d_in[10];
    const float* sa_out_w  = (const float*)d_in[11];
    const float* sa_out_b  = (const float*)d_in[12];
    const float* ca_in_w   = (const float*)d_in[13];
    const float* ca_in_b   = (const float*)d_in[14];
    const float* ca_out_w  = (const float*)d_in[15];
    const float* ca_out_b  = (const float*)d_in[16];
    const float* lin1_w    = (const float*)d_in[17];
    const float* lin1_b    = (const float*)d_in[18];
    const float* lin2_w    = (const float*)d_in[19];
    const float* lin2_b    = (const float*)d_in[20];
    const float* ln1_s     = (const float*)d_in[21];
    const float* ln1_b     = (const float*)d_in[22];
    const float* ln2_s     = (const float*)d_in[23];
    const float* ln2_b     = (const float*)d_in[24];
    const float* ln3_s     = (const float*)d_in[25];
    const float* ln3_b     = (const float*)d_in[26];

    float *x, *xc, *memc, *q, *k, *v, *ql, *sc, *o, *tmp, *x1, *x1c, *x2, *x2c, *ffn, *wts;
    cudaGetSymbolAddress((void**)&x,    g_x);
    cudaGetSymbolAddress((void**)&xc,   g_xc);
    cudaGetSymbolAddress((void**)&memc, g_memc);
    cudaGetSymbolAddress((void**)&q,    g_q);
    cudaGetSymbolAddress((void**)&k,    g_k);
    cudaGetSymbolAddress((void**)&v,    g_v);
    cudaGetSymbolAddress((void**)&ql,   g_ql);
    cudaGetSymbolAddress((void**)&sc,   g_sc);
    cudaGetSymbolAddress((void**)&o,    g_o);
    cudaGetSymbolAddress((void**)&tmp,  g_tmp);
    cudaGetSymbolAddress((void**)&x1,   g_x1);
    cudaGetSymbolAddress((void**)&x1c,  g_x1c);
    cudaGetSymbolAddress((void**)&x2,   g_x2);
    cudaGetSymbolAddress((void**)&x2c,  g_x2c);
    cudaGetSymbolAddress((void**)&ffn,  g_ffn);
    cudaGetSymbolAddress((void**)&wts,  g_wts);

    static int attrDone = 0;
    if (!attrDone) {
        cudaFuncSetAttribute(gemm_nt, cudaFuncAttributeMaxDynamicSharedMemorySize, SM_GEMM);
        cudaFuncSetAttribute(ql_kernel, cudaFuncAttributeMaxDynamicSharedMemorySize, SM_GEMM);
        cudaFuncSetAttribute(ca_scores_kernel, cudaFuncAttributeMaxDynamicSharedMemorySize, SM_GEMM);
        cudaFuncSetAttribute(sa_scores_kernel, cudaFuncAttributeMaxDynamicSharedMemorySize, SM_SA);
        cudaFuncSetAttribute(attn_v_kernel, cudaFuncAttributeMaxDynamicSharedMemorySize, SM_AV);
        attrDone = 1;
    }

    // weight rounding pass
    CvtParams cp;
    cp.j[0] = { sa_q_w,   wts + WQ_OFF,   D_ * D_ };
    cp.j[1] = { sa_k_w,   wts + WK_OFF,   D_ * D_ };
    cp.j[2] = { sa_v_w,   wts + WV_OFF,   D_ * D_ };
    cp.j[3] = { sa_out_w, wts + WO_OFF,   D_ * D_ };
    cp.j[4] = { ca_in_w,  wts + WCA_OFF,  3 * D_ * D_ };
    cp.j[5] = { ca_out_w, wts + WCAO_OFF, D_ * D_ };
    cp.j[6] = { lin1_w,   wts + WL1_OFF,  F_ * D_ };
    cp.j[7] = { lin2_w,   wts + WL2_OFF,  D_ * F_ };
    cp.j[8] = { sa_rel,   wts + WREL_OFF, L_ * HD_ * HD_ };
    cvt_weights<<<dim3(1024, 9), 256>>>(cp);

    const dim3 gproj(D_ / 64, (B_ * T_) / 128, 1);    // (8, 32)
    const dim3 gqkv (D_ / 64, (B_ * T_) / 128, 3);    // (8, 32, 3)
    const dim3 gattn(T_ / 64, T_ / 128, B_ * H_);     // (8, 4, 64)
    const dim3 gav(1, T_ / 128, B_ * H_);             // (1, 4, 64)

    // --- self-attention ---
    transpose_tb<<<T_ * B_, 128>>>(tgt, x, xc, T_);
    transpose_tb<<<S_ * B_, 128>>>(memory, nullptr, memc, S_);
    gemm_nt<<<gqkv, 256, SM_GEMM>>>(
        mkg(xc, wts + WQ_OFF, sa_q_b, nullptr, q,
            xc, wts + WK_OFF, sa_k_b, k,
            xc, wts + WV_OFF, sa_v_b, v, D_, D_, D_, D_, 0, 1));
    ql_kernel<<<dim3(L_ * B_ * H_, T_ / 128), 256, SM_GEMM>>>(q, wts + WREL_OFF, ql);
    sa_scores_kernel<<<gattn, 256, SM_SA>>>(ql, k, em, pad, sc);
    softmax_kernel<<<B_ * H_ * T_, 256>>>(sc);
    attn_v_kernel<<<gav, 256, SM_AV>>>(sc, v, o, T_);
    gemm_nt<<<gproj, 256, SM_GEMM>>>(
        mkg(o, wts + WO_OFF, sa_out_b, x, tmp,
            nullptr, nullptr, nullptr, nullptr,
            nullptr, nullptr, nullptr, nullptr, D_, D_, D_, D_, 0, 0));
    ln_kernel<<<B_ * T_, 128>>>(tmp, ln1_s, ln1_b, x1, x1c, 0);

    // --- cross-attention ---
    gemm_nt<<<gqkv, 256, SM_GEMM>>>(
        mkg(x1c,  wts + WCA_OFF,              ca_in_b,          nullptr, q,
            memc, wts + WCA_OFF + D_ * D_,    ca_in_b + D_,     k,
            memc, wts + WCA_OFF + 2 * D_ * D_, ca_in_b + 2 * D_, v, D_, D_, D_, D_, 0, 1));
    ca_scores_kernel<<<dim3(S_ / 64, T_ / 128, B_ * H_), 256, SM_GEMM>>>(q, k, sc);
    softmax_kernel<<<B_ * H_ * T_, 256>>>(sc);
    attn_v_kernel<<<gav, 256, SM_AV>>>(sc, v, o, S_);
    gemm_nt<<<gproj, 256, SM_GEMM>>>(
        mkg(o, wts + WCAO_OFF, ca_out_b, x1, tmp,
            nullptr, nullptr, nullptr, nullptr,
            nullptr, nullptr, nullptr, nullptr, D_, D_, D_, D_, 0, 0));
    ln_kernel<<<B_ * T_, 128>>>(tmp, ln2_s, ln2_b, x2, x2c, 0);

    // --- FFN ---
    gemm_nt<<<dim3(F_ / 64, (B_ * T_) / 128, 1), 256, SM_GEMM>>>(
        mkg(x2c, wts + WL1_OFF, lin1_b, nullptr, ffn,
            nullptr, nullptr, nullptr, nullptr,
            nullptr, nullptr, nullptr, nullptr, D_, D_, F_, D_, 1, 1));
    gemm_nt<<<gproj, 256, SM_GEMM>>>(
        mkg(ffn, wts + WL2_OFF, lin2_b, x2, tmp,
            nullptr, nullptr, nullptr, nullptr,
            nullptr, nullptr, nullptr, nullptr, F_, F_, D_, F_, 0, 0));
    ln_kernel<<<B_ * T_, 128>>>(tmp, ln3_s, ln3_b, (float*)d_out, nullptr, 1);
}

// round 11
// speedup vs baseline: 3.5548x; 1.4616x over previous
#include <cuda_runtime.h>
#include <cuda_fp16.h>

#define T_ 512
#define S_ 512
#define B_ 8
#define D_ 512
#define H_ 8
#define HD_ 64
#define L_ 8
#define F_ 2048

// ---------------- scratch (device globals; no runtime allocation) ----------------
__device__ float  g_x  [B_*T_*D_];      // raw tgt (B,T,D) for residual
__device__ __half g_xh [B_*T_*D_];
__device__ __half g_memh[B_*S_*D_];
__device__ __half g_qh [B_*T_*D_];
__device__ __half g_kh [B_*S_*D_];
__device__ __half g_vth[D_*B_*S_];      // v^T : [channel][b*S+j]
__device__ __half g_qlh[L_*B_*T_*D_];
__device__ float  g_sc [B_*H_*T_*T_];
__device__ __half g_sch[B_*H_*T_*T_];
__device__ __half g_oh [B_*T_*D_];
__device__ float  g_tmp[B_*T_*D_];
__device__ float  g_x1 [B_*T_*D_];
__device__ __half g_x1h[B_*T_*D_];
__device__ float  g_x2 [B_*T_*D_];
__device__ __half g_x2h[B_*T_*D_];
__device__ __half g_ffnh[B_*T_*F_];
__device__ __half g_wtsh[4227072];

#define WQ_OFF   0
#define WK_OFF   262144
#define WV_OFF   524288
#define WO_OFF   786432
#define WCA_OFF  1048576
#define WCAO_OFF 1835008
#define WL1_OFF  2097152
#define WL2_OFF  3145728
#define WREL_OFF 4194304

// ---------------- cp.async helpers ----------------
__device__ __forceinline__ void cp16(unsigned dst, const void* src) {
    asm volatile("cp.async.ca.shared.global [%0], [%1], 16;" :: "r"(dst), "l"(src));
}
#define CP_COMMIT() asm volatile("cp.async.commit_group;" ::: "memory")
#define CP_WAIT0()  asm volatile("cp.async.wait_group 0;" ::: "memory")
#define CP_WAIT1()  asm volatile("cp.async.wait_group 1;" ::: "memory")

// smem: K-chunk = 32 halves. AST/WST = 48 halves (96B rows) -> conflict-free LDS.64
#define AST 48
#define WST 48
#define ABYTES (128*AST*2)   // 12288
#define WBYTES (64*WST*2)    // 6144
#define SM_GEMM (3*(ABYTES+WBYTES))   // 55296
#define SM_SA   (2*ABYTES+2*WBYTES)   // 36864

// A chunk: 128 rows x 32 halves (64B) = 512 segs of 16B; 256 threads x2
__device__ __forceinline__ void cpA(unsigned dst, const __half* __restrict__ Ab,
                                    int lda, int k0, int tid)
{
#pragma unroll
    for (int i = 0; i < 2; i++) {
        int idx = tid + i * 256;
        int row = idx >> 2, seg = idx & 3;
        cp16(dst + row * (AST * 2) + seg * 16, Ab + (size_t)row * lda + k0 + seg * 8);
    }
}
// W chunk: 64 rows x 32 halves = 256 segs
__device__ __forceinline__ void cpW(unsigned dst, const __half* __restrict__ Wb,
                                    int ldw, int k0, int tid)
{
    int row = tid >> 2, seg = tid & 3;
    cp16(dst + row * (WST * 2) + seg * 16, Wb + (size_t)row * ldw + k0 + seg * 8);
}

// ---------------- fp16 mma core: one K=32 chunk of a 128x64 tile ----------------
__device__ __forceinline__ void mma16(float* c, const unsigned* a, const unsigned* b) {
    asm volatile(
        "mma.sync.aligned.m16n8k16.row.col.f32.f16.f16.f32 "
        "{%0,%1,%2,%3}, {%4,%5,%6,%7}, {%8,%9}, {%0,%1,%2,%3};"
        : "+f"(c[0]), "+f"(c[1]), "+f"(c[2]), "+f"(c[3])
        : "r"(a[0]), "r"(a[1]), "r"(a[2]), "r"(a[3]), "r"(b[0]), "r"(b[1]));
}

// k-permuted: hw k-pair (2q,2q+1)->logical (4q,4q+1); (2q+8,2q+9)->(4q+2,4q+3).
// Same permutation on A and B => exact dot product. One LDS.64 per fragment pair.
__device__ __forceinline__ void mma_chunk_nt(
    const __half* __restrict__ As, const __half* __restrict__ Ws,
    int warp_m, int warp_n, int lane, float c[2][4][4])
{
    int r = lane >> 2, q = lane & 3;
    const __half* Ap = As + (warp_m + r) * AST + 4 * q;
    const __half* Bp = Ws + (warp_n + r) * WST + 4 * q;
#pragma unroll
    for (int kg = 0; kg < 2; kg++) {
        int kb = kg * 16;
        unsigned a[2][4], b[4][2];
#pragma unroll
        for (int mf = 0; mf < 2; mf++) {
            uint2 lo = *(const uint2*)(Ap + (mf * 16) * AST + kb);
            uint2 hi = *(const uint2*)(Ap + (mf * 16 + 8) * AST + kb);
            a[mf][0] = lo.x; a[mf][1] = hi.x; a[mf][2] = lo.y; a[mf][3] = hi.y;
        }
#pragma unroll
        for (int nf = 0; nf < 4; nf++) {
            uint2 bb = *(const uint2*)(Bp + nf * 8 * WST + kb);
            b[nf][0] = bb.x; b[nf][1] = bb.y;
        }
#pragma unroll
        for (int mf = 0; mf < 2; mf++)
#pragma unroll
            for (int nf = 0; nf < 4; nf++)
                mma16(c[mf][nf], a[mf], b[nf]);
    }
}

// ---------------- batched dense NT GEMM (3-stage cp.async, up to 3 jobs via z) ----------------
struct GJob {
    const __half* A; const __half* W;
    const float* bias; const float* res;
    float* Cf; __half* Ch;
    int lda, ldw, ldc, K, gx, biasMode, relu;
};
struct GParams { GJob j[3]; };

__global__ __launch_bounds__(256) void gemm_nt(GParams g)
{
    extern __shared__ __half sm[];
    __half* As = sm;
    __half* Ws = sm + 3 * 128 * AST;
    const GJob J = g.j[blockIdx.z];
    int tid = threadIdx.x, w = tid >> 5, lane = tid & 31;
    int warp_m = (w >> 1) * 32, warp_n = (w & 1) * 32;
    int bx = blockIdx.x % J.gx, by = blockIdx.x / J.gx;
    int row0 = by * 128, col0 = bx * 64;
    const __half* Ab = J.A + (size_t)row0 * J.lda;
    const __half* Wb = J.W + (size_t)col0 * J.ldw;
    unsigned sA = (unsigned)__cvta_generic_to_shared(As);
    unsigned sW = (unsigned)__cvta_generic_to_shared(Ws);
    float c[2][4][4] = {};
    int nch = J.K >> 5;
#pragma unroll
    for (int s = 0; s < 2; s++) {
        cpA(sA + s * ABYTES, Ab, J.lda, s << 5, tid);
        cpW(sW + s * WBYTES, Wb, J.ldw, s << 5, tid);
        CP_COMMIT();
    }
    for (int ch = 0; ch < nch; ch++) {
        if (ch < nch - 1) { CP_WAIT1(); } else { CP_WAIT0(); }
        __syncthreads();
        int nx = ch + 2;
        if (nx < nch) {
            int bs = nx % 3;
            cpA(sA + bs * ABYTES, Ab, J.lda, nx << 5, tid);
            cpW(sW + bs * WBYTES, Wb, J.ldw, nx << 5, tid);
            CP_COMMIT();
        }
        mma_chunk_nt(As + (ch % 3) * 128 * AST, Ws + (ch % 3) * 64 * WST,
                     warp_m, warp_n, lane, c);
    }
    int r = lane >> 2, q = lane & 3;
#pragma unroll
    for (int mf = 0; mf < 2; mf++)
#pragma unroll
    for (int rr = 0; rr < 2; rr++) {
        int row = row0 + warp_m + mf * 16 + r + rr * 8;
        float rb = (J.biasMode == 2) ? J.bias[row] : 0.f;
#pragma unroll
        for (int nf = 0; nf < 4; nf++) {
            int col = col0 + warp_n + nf * 8 + 2 * q;
            float2 o = make_float2(c[mf][nf][2 * rr], c[mf][nf][2 * rr + 1]);
            if (J.biasMode == 1) {
                float2 bb = *(const float2*)(J.bias + col);
                o.x += bb.x; o.y += bb.y;
            } else if (J.biasMode == 2) { o.x += rb; o.y += rb; }
            if (J.res) {
                float2 rv = *(const float2*)(J.res + (size_t)row * J.ldc + col);
                o.x += rv.x; o.y += rv.y;
            }
            if (J.relu) { o.x = fmaxf(o.x, 0.f); o.y = fmaxf(o.y, 0.f); }
            if (J.Cf) *(float2*)(J.Cf + (size_t)row * J.ldc + col) = o;
            if (J.Ch) *((__half2*)(J.Ch + (size_t)row * J.ldc + col)) =
                          __floats2half2_rn(o.x, o.y);
        }
    }
}

// ---------------- ql[l,b,t,h*64+e] = q @ rel[l]^T (half out) ----------------
__global__ __launch_bounds__(256) void ql_kernel(
    const __half* __restrict__ qm, const __half* __restrict__ rel, __half* __restrict__ qlb)
{
    extern __shared__ __half sm[];
    __half* As = sm;
    __half* Ws = sm + 3 * 128 * AST;
    int z = blockIdx.x;                       // l*64 + b*8 + h
    int h = z & 7, b = (z >> 3) & 7, l = z >> 6;
    int i0 = blockIdx.y * 128;
    int tid = threadIdx.x, w = tid >> 5, lane = tid & 31;
    int warp_m = (w >> 1) * 32, warp_n = (w & 1) * 32;
    const __half* Ab = qm + (size_t)(b * T_ + i0) * D_ + h * HD_;
    const __half* Wb = rel + (size_t)l * HD_ * HD_;
    unsigned sA = (unsigned)__cvta_generic_to_shared(As);
    unsigned sW = (unsigned)__cvta_generic_to_shared(Ws);
    float c[2][4][4] = {};
    const int nch = 2;   // K=64
#pragma unroll
    for (int s = 0; s < 2; s++) {
        cpA(sA + s * ABYTES, Ab, D_, s << 5, tid);
        cpW(sW + s * WBYTES, Wb, HD_, s << 5, tid);
        CP_COMMIT();
    }
#pragma unroll
    for (int ch = 0; ch < nch; ch++) {
        if (ch < nch - 1) { CP_WAIT1(); } else { CP_WAIT0(); }
        __syncthreads();
        mma_chunk_nt(As + ch * 128 * AST, Ws + ch * 64 * WST, warp_m, warp_n, lane, c);
    }
    int r = lane >> 2, q = lane & 3;
    __half* Ob = qlb + (size_t)((l * B_ + b) * T_ + i0) * D_ + h * HD_;
#pragma unroll
    for (int mf = 0; mf < 2; mf++)
#pragma unroll
    for (int rr = 0; rr < 2; rr++) {
        int row = warp_m + mf * 16 + r + rr * 8;
#pragma unroll
        for (int nf = 0; nf < 4; nf++) {
            int col = warp_n + nf * 8 + 2 * q;
            *((__half2*)(Ob + (size_t)row * D_ + col)) =
                __floats2half2_rn(c[mf][nf][2 * rr], c[mf][nf][2 * rr + 1]);
        }
    }
}

// ---------------- sa scores: persistent K tile (2 chunks), 2-stage A ring ----------------
__global__ __launch_bounds__(256) void sa_scores_kernel(
    const __half* __restrict__ qlb, const __half* __restrict__ km,
    const float* __restrict__ em, const unsigned char* __restrict__ pad,
    float* __restrict__ sc)
{
    extern __shared__ __half sm[];
    __half* As = sm;
    __half* Ws2 = sm + 2 * 128 * AST;
    int z = blockIdx.z; int h = z & 7, b = z >> 3;
    int i0 = blockIdx.y * 128, j0 = blockIdx.x * 64;
    int tid = threadIdx.x, w = tid >> 5, lane = tid & 31;
    int warp_m = (w >> 1) * 32, warp_n = (w & 1) * 32;
    int r = lane >> 2, q = lane & 3;
    unsigned sA = (unsigned)__cvta_generic_to_shared(As);
    unsigned sW = (unsigned)__cvta_generic_to_shared(Ws2);
    const __half* Kb = km + (size_t)(b * T_ + j0) * D_ + h * HD_;
    const __half* A0 = qlb + (size_t)(b * T_ + i0) * D_ + h * HD_;
    const size_t LSTR = (size_t)B_ * T_ * D_;
    cpW(sW, Kb, D_, 0, tid);
    cpW(sW + WBYTES, Kb, D_, 32, tid);
    cpA(sA, A0, D_, 0, tid);
    CP_COMMIT();

    float acc[2][4][4] = {};
    int cc = 0;
    for (int l = 0; l < L_; l++) {
        float c[2][4][4] = {};
#pragma unroll
        for (int kc = 0; kc < 2; kc++) {
            CP_WAIT0();
            __syncthreads();
            bool have_next = (cc < 15);
            if (have_next) {
                int nl = kc ? l + 1 : l;
                int nk = kc ? 0 : 1;
                cpA(sA + ((cc + 1) & 1) * ABYTES, A0 + (size_t)nl * LSTR, D_, nk << 5, tid);
                CP_COMMIT();
            }
            mma_chunk_nt(As + (cc & 1) * 128 * AST, Ws2 + kc * 64 * WST,
                         warp_m, warp_n, lane, c);
            cc++;
        }
        const float* emb = em + (size_t)(b * L_ + l) * T_ * T_;
#pragma unroll
        for (int mf = 0; mf < 2; mf++)
#pragma unroll
        for (int rr = 0; rr < 2; rr++) {
            int i = i0 + warp_m + mf * 16 + r + rr * 8;
#pragma unroll
            for (int nf = 0; nf < 4; nf++) {
                int j = j0 + warp_n + nf * 8 + 2 * q;
                float2 e = *(const float2*)(emb + (size_t)i * T_ + j);
                acc[mf][nf][2 * rr]     += e.x * c[mf][nf][2 * rr];
                acc[mf][nf][2 * rr + 1] += e.y * c[mf][nf][2 * rr + 1];
            }
        }
    }
#pragma unroll
    for (int mf = 0; mf < 2; mf++)
#pragma unroll
    for (int rr = 0; rr < 2; rr++) {
        int i = i0 + warp_m + mf * 16 + r + rr * 8;
#pragma unroll
        for (int nf = 0; nf < 4; nf++) {
            int j = j0 + warp_n + nf * 8 + 2 * q;
            const unsigned char* pp = pad + (size_t)(b * T_ + i) * T_ + j;
            float2 o;
            o.x = pp[0] ? -1e9f : acc[mf][nf][2 * rr] * 0.125f;
            o.y = pp[1] ? -1e9f : acc[mf][nf][2 * rr + 1] * 0.125f;
            *(float2*)(sc + ((size_t)z * T_ + i) * T_ + j) = o;
        }
    }
}

// ---------------- cross scores: (cq . ck^T) * scale ----------------
__global__ __launch_bounds__(256) void ca_scores_kernel(
    const __half* __restrict__ cq, const __half* __restrict__ ck, float* __restrict__ sc)
{
    extern __shared__ __half sm[];
    __half* As = sm;
    __half* Ws = sm + 3 * 128 * AST;
    int z = blockIdx.z; int h = z & 7, b = z >> 3;
    int i0 = blockIdx.y * 128, j0 = blockIdx.x * 64;
    int tid = threadIdx.x, w = tid >> 5, lane = tid & 31;
    int warp_m = (w >> 1) * 32, warp_n = (w & 1) * 32;
    const __half* Ab = cq + (size_t)(b * T_ + i0) * D_ + h * HD_;
    const __half* Wb = ck + (size_t)(b * S_ + j0) * D_ + h * HD_;
    unsigned sA = (unsigned)__cvta_generic_to_shared(As);
    unsigned sW = (unsigned)__cvta_generic_to_shared(Ws);
    float c[2][4][4] = {};
    const int nch = 2;   // K=64
#pragma unroll
    for (int s = 0; s < 2; s++) {
        cpA(sA + s * ABYTES, Ab, D_, s << 5, tid);
        cpW(sW + s * WBYTES, Wb, D_, s << 5, tid);
        CP_COMMIT();
    }
#pragma unroll
    for (int ch = 0; ch < nch; ch++) {
        if (ch < nch - 1) { CP_WAIT1(); } else { CP_WAIT0(); }
        __syncthreads();
        mma_chunk_nt(As + ch * 128 * AST, Ws + ch * 64 * WST, warp_m, warp_n, lane, c);
    }
    int r = lane >> 2, q = lane & 3;
#pragma unroll
    for (int mf = 0; mf < 2; mf++)
#pragma unroll
    for (int rr = 0; rr < 2; rr++) {
        int i = i0 + warp_m + mf * 16 + r + rr * 8;
#pragma unroll
        for (int nf = 0; nf < 4; nf++) {
            int j = j0 + warp_n + nf * 8 + 2 * q;
            *(float2*)(sc + ((size_t)z * T_ + i) * S_ + j) =
                make_float2(c[mf][nf][2 * rr] * 0.125f, c[mf][nf][2 * rr + 1] * 0.125f);
        }
    }
}

// ---------------- row softmax over width 512: float in -> half out ----------------
__global__ void softmax_kernel(const float* __restrict__ sc, __half* __restrict__ sch)
{
    __shared__ float red[8];
    int row = blockIdx.x;
    int tid = threadIdx.x;
    const float* p = sc + (size_t)row * 512;
    __half* ph = sch + (size_t)row * 512;
    float a0 = p[tid], a1 = p[tid + 256];
    float m = fmaxf(a0, a1);
#pragma unroll
    for (int o = 16; o; o >>= 1) m = fmaxf(m, __shfl_xor_sync(0xffffffffu, m, o));
    if ((tid & 31) == 0) red[tid >> 5] = m;
    __syncthreads();
    m = red[0];
#pragma unroll
    for (int i = 1; i < 8; i++) m = fmaxf(m, red[i]);
    float e0 = __expf(a0 - m), e1 = __expf(a1 - m);
    float s = e0 + e1;
#pragma unroll
    for (int o = 16; o; o >>= 1) s += __shfl_xor_sync(0xffffffffu, s, o);
    __syncthreads();
    if ((tid & 31) == 0) red[tid >> 5] = s;
    __syncthreads();
    s = red[0] + red[1] + red[2] + red[3] + red[4] + red[5] + red[6] + red[7];
    float inv = 1.0f / s;
    ph[tid] = __float2half_rn(e0 * inv);
    ph[tid + 256] = __float2half_rn(e1 * inv);
}

// ---------------- o = attn @ v via NT with v^T (half out) ----------------
__global__ __launch_bounds__(256) void attn_v_kernel(
    const __half* __restrict__ attn, const __half* __restrict__ vt,
    __half* __restrict__ o, int kdim)
{
    extern __shared__ __half sm[];
    __half* As = sm;
    __half* Ws = sm + 3 * 128 * AST;
    int z = blockIdx.z; int h = z & 7, b = z >> 3;
    int i0 = blockIdx.y * 128;
    int tid = threadIdx.x, w = tid >> 5, lane = tid & 31;
    int warp_m = (w >> 1) * 32, warp_n = (w & 1) * 32;
    const __half* Ab = attn + (size_t)z * T_ * kdim + (size_t)i0 * kdim;
    const __half* Wb = vt + (size_t)(h * HD_) * (B_ * kdim) + (size_t)b * kdim;
    int ldw = B_ * kdim;
    unsigned sA = (unsigned)__cvta_generic_to_shared(As);
    unsigned sW = (unsigned)__cvta_generic_to_shared(Ws);
    float c[2][4][4] = {};
    int nch = kdim >> 5;
#pragma unroll
    for (int s = 0; s < 2; s++) {
        cpA(sA + s * ABYTES, Ab, kdim, s << 5, tid);
        cpW(sW + s * WBYTES, Wb, ldw, s << 5, tid);
        CP_COMMIT();
    }
    for (int ch = 0; ch < nch; ch++) {
        if (ch < nch - 1) { CP_WAIT1(); } else { CP_WAIT0(); }
        __syncthreads();
        int nx = ch + 2;
        if (nx < nch) {
            int bs = nx % 3;
            cpA(sA + bs * ABYTES, Ab, kdim, nx << 5, tid);
            cpW(sW + bs * WBYTES, Wb, ldw, nx << 5, tid);
            CP_COMMIT();
        }
        mma_chunk_nt(As + (ch % 3) * 128 * AST, Ws + (ch % 3) * 64 * WST,
                     warp_m, warp_n, lane, c);
    }
    int r = lane >> 2, q = lane & 3;
    __half* Ob = o + (size_t)(b * T_ + i0) * D_ + h * HD_;
#pragma unroll
    for (int mf = 0; mf < 2; mf++)
#pragma unroll
    for (int rr = 0; rr < 2; rr++) {
        int row = warp_m + mf * 16 + r + rr * 8;
#pragma unroll
        for (int nf = 0; nf < 4; nf++) {
            int col = warp_n + nf * 8 + 2 * q;
            *((__half2*)(Ob + (size_t)row * D_ + col)) =
                __floats2half2_rn(c[mf][nf][2 * rr], c[mf][nf][2 * rr + 1]);
        }
    }
}

// ---------------- (T,B,D) -> (B,T,D) gather; raw float (optional) + half ----------------
__global__ void transpose_tb(const float* __restrict__ in, float* __restrict__ out_raw,
                             __half* __restrict__ out_h, int Tdim)
{
    int row = blockIdx.x;
    int t = row / B_, b = row - t * B_;
    float4 v = ((const float4*)(in + (size_t)(t * B_ + b) * D_))[threadIdx.x];
    size_t off = (size_t)(b * Tdim + t) * D_;
    if (out_raw) ((float4*)(out_raw + off))[threadIdx.x] = v;
    __half2* hp = (__half2*)(out_h + off + threadIdx.x * 4);
    hp[0] = __floats2half2_rn(v.x, v.y);
    hp[1] = __floats2half2_rn(v.z, v.w);
}

// ---------------- LayerNorm over D=512; raw float + optional half ----------------
__global__ void ln_kernel(const float* __restrict__ in, const float* __restrict__ sg,
                          const float* __restrict__ bg, float* __restrict__ out,
                          __half* __restrict__ out_h, int transpose)
{
    __shared__ float red[4];
    int row = blockIdx.x;
    int tid = threadIdx.x;
    const float* x = in + (size_t)row * D_;
    float v[4];
#pragma unroll
    for (int i = 0; i < 4; i++) v[i] = x[tid + i * 128];
    float s = v[0] + v[1] + v[2] + v[3];
#pragma unroll
    for (int o = 16; o; o >>= 1) s += __shfl_xor_sync(0xffffffffu, s, o);
    if ((tid & 31) == 0) red[tid >> 5] = s;
    __syncthreads();
    float mean = (red[0] + red[1] + red[2] + red[3]) * (1.0f / D_);
    __syncthreads();
    float qv = 0.f;
#pragma unroll
    for (int i = 0; i < 4; i++) { float d = v[i] - mean; qv += d * d; }
#pragma unroll
    for (int o = 16; o; o >>= 1) qv += __shfl_xor_sync(0xffffffffu, qv, o);
    if ((tid & 31) == 0) red[tid >> 5] = qv;
    __syncthreads();
    float var = (red[0] + red[1] + red[2] + red[3]) * (1.0f / D_);
    float inv = rsqrtf(var + 1e-5f);
    int orow = row;
    if (transpose) { int b = row / T_; int t = row - b * T_; orow = t * B_ + b; }
    float* op = out + (size_t)orow * D_;
    __half* oph = out_h ? out_h + (size_t)orow * D_ : nullptr;
#pragma unroll
    for (int i = 0; i < 4; i++) {
        int d = tid + i * 128;
        float val = (v[i] - mean) * inv * sg[d] + bg[d];
        op[d] = val;
        if (oph) oph[d] = __float2half_rn(val);
    }
}

// ---------------- weight float -> half pass ----------------
struct CvtJob { const float* src; __half* dst; int n; };
struct CvtParams { CvtJob j[9]; };
__global__ void cvt_weights(CvtParams p)
{
    const CvtJob J = p.j[blockIdx.y];
    int i = (blockIdx.x * 256 + threadIdx.x) * 4;
    if (i < J.n) {
        float4 v = *(const float4*)(J.src + i);
        __half2* d = (__half2*)(J.dst + i);
        d[0] = __floats2half2_rn(v.x, v.y);
        d[1] = __floats2half2_rn(v.z, v.w);
    }
}

// ---------------- launch ----------------
extern "C" void kernel_launch(void* const* d_in, const int* in_sizes, int n_in,
                              void* d_out, int out_size)
{
    const float* tgt       = (const float*)d_in[0];
    const float* em        = (const float*)d_in[1];
    const unsigned char* pad = (const unsigned char*)d_in[2];
    const float* memory    = (const float*)d_in[3];
    const float* sa_q_w    = (const float*)d_in[4];
    const float* sa_q_b    = (const float*)d_in[5];
    const float* sa_k_w    = (const float*)d_in[6];
    const float* sa_k_b    = (const float*)d_in[7];
    const float* sa_v_w    = (const float*)d_in[8];
    const float* sa_v_b    = (const float*)d_in[9];
    const float* sa_rel    = (const float*)d_in[10];
    const float* sa_out_w  = (const float*)d_in[11];
    const float* sa_out_b  = (const float*)d_in[12];
    const float* ca_in_w   = (const float*)d_in[13];
    const float* ca_in_b   = (const float*)d_in[14];
    const float* ca_out_w  = (const float*)d_in[15];
    const float* ca_out_b  = (const float*)d_in[16];
    const float* lin1_w    = (const float*)d_in[17];
    const float* lin1_b    = (const float*)d_in[18];
    const float* lin2_w    = (const float*)d_in[19];
    const float* lin2_b    = (const float*)d_in[20];
    const float* ln1_s     = (const float*)d_in[21];
    const float* ln1_b     = (const float*)d_in[22];
    const float* ln2_s     = (const float*)d_in[23];
    const float* ln2_b     = (const float*)d_in[24];
    const float* ln3_s     = (const float*)d_in[25];
    const float* ln3_b     = (const float*)d_in[26];

    float *x, *sc, *tmp, *x1, *x2;
    __half *xh, *memh, *qh, *kh, *vth, *qlh, *sch, *oh, *x1h, *x2h, *ffnh, *wh;
    cudaGetSymbolAddress((void**)&x,    g_x);
    cudaGetSymbolAddress((void**)&xh,   g_xh);
    cudaGetSymbolAddress((void**)&memh, g_memh);
    cudaGetSymbolAddress((void**)&qh,   g_qh);
    cudaGetSymbolAddress((void**)&kh,   g_kh);
    cudaGetSymbolAddress((void**)&vth,  g_vth);
    cudaGetSymbolAddress((void**)&qlh,  g_qlh);
    cudaGetSymbolAddress((void**)&sc,   g_sc);
    cudaGetSymbolAddress((void**)&sch,  g_sch);
    cudaGetSymbolAddress((void**)&oh,   g_oh);
    cudaGetSymbolAddress((void**)&tmp,  g_tmp);
    cudaGetSymbolAddress((void**)&x1,   g_x1);
    cudaGetSymbolAddress((void**)&x1h,  g_x1h);
    cudaGetSymbolAddress((void**)&x2,   g_x2);
    cudaGetSymbolAddress((void**)&x2h,  g_x2h);
    cudaGetSymbolAddress((void**)&ffnh, g_ffnh);
    cudaGetSymbolAddress((void**)&wh,   g_wtsh);

    static int attrDone = 0;
    if (!attrDone) {
        cudaFuncSetAttribute(gemm_nt, cudaFuncAttributeMaxDynamicSharedMemorySize, SM_GEMM);
        cudaFuncSetAttribute(ql_kernel, cudaFuncAttributeMaxDynamicSharedMemorySize, SM_GEMM);
        cudaFuncSetAttribute(ca_scores_kernel, cudaFuncAttributeMaxDynamicSharedMemorySize, SM_GEMM);
        cudaFuncSetAttribute(attn_v_kernel, cudaFuncAttributeMaxDynamicSharedMemorySize, SM_GEMM);
        cudaFuncSetAttribute(sa_scores_kernel, cudaFuncAttributeMaxDynamicSharedMemorySize, SM_SA);
        attrDone = 1;
    }

    CvtParams cp;
    cp.j[0] = { sa_q_w,   wh + WQ_OFF,   D_ * D_ };
    cp.j[1] = { sa_k_w,   wh + WK_OFF,   D_ * D_ };
    cp.j[2] = { sa_v_w,   wh + WV_OFF,   D_ * D_ };
    cp.j[3] = { sa_out_w, wh + WO_OFF,   D_ * D_ };
    cp.j[4] = { ca_in_w,  wh + WCA_OFF,  3 * D_ * D_ };
    cp.j[5] = { ca_out_w, wh + WCAO_OFF, D_ * D_ };
    cp.j[6] = { lin1_w,   wh + WL1_OFF,  F_ * D_ };
    cp.j[7] = { lin2_w,   wh + WL2_OFF,  D_ * F_ };
    cp.j[8] = { sa_rel,   wh + WREL_OFF, L_ * HD_ * HD_ };
    cvt_weights<<<dim3(1024, 9), 256>>>(cp);

    GParams g;

    // --- self-attention ---
    transpose_tb<<<T_ * B_, 128>>>(tgt, x, xh, T_);
    transpose_tb<<<S_ * B_, 128>>>(memory, nullptr, memh, S_);
    // QKV: q,k standard NT; v as v^T = Wv @ x^T (per-row bias)
    g.j[0] = { xh, wh + WQ_OFF, sa_q_b, nullptr, nullptr, qh, D_, D_, D_, D_, 8, 1, 0 };
    g.j[1] = { xh, wh + WK_OFF, sa_k_b, nullptr, nullptr, kh, D_, D_, D_, D_, 8, 1, 0 };
    g.j[2] = { wh + WV_OFF, xh, sa_v_b, nullptr, nullptr, vth, D_, D_, B_ * T_, D_, 64, 2, 0 };
    gemm_nt<<<dim3(256, 1, 3), 256, SM_GEMM>>>(g);
    ql_kernel<<<dim3(L_ * B_ * H_, T_ / 128), 256, SM_GEMM>>>(qh, wh + WREL_OFF, qlh);
    sa_scores_kernel<<<dim3(T_ / 64, T_ / 128, B_ * H_), 256, SM_SA>>>(qlh, kh, em, pad, sc);
    softmax_kernel<<<B_ * H_ * T_, 256>>>(sc, sch);
    attn_v_kernel<<<dim3(1, T_ / 128, B_ * H_), 256, SM_GEMM>>>(sch, vth, oh, T_);
    g.j[0] = { oh, wh + WO_OFF, sa_out_b, x, tmp, nullptr, D_, D_, D_, D_, 8, 1, 0 };
    gemm_nt<<<dim3(256, 1, 1), 256, SM_GEMM>>>(g);
    ln_kernel<<<B_ * T_, 128>>>(tmp, ln1_s, ln1_b, x1, x1h, 0);

    // --- cross-attention ---
    g.j[0] = { x1h,  wh + WCA_OFF,              ca_in_b,          nullptr, nullptr, qh,  D_, D_, D_, D_, 8, 1, 0 };
    g.j[1] = { memh, wh + WCA_OFF + D_ * D_,    ca_in_b + D_,     nullptr, nullptr, kh,  D_, D_, D_, D_, 8, 1, 0 };
    g.j[2] = { wh + WCA_OFF + 2 * D_ * D_, memh, ca_in_b + 2 * D_, nullptr, nullptr, vth, D_, D_, B_ * S_, D_, 64, 2, 0 };
    gemm_nt<<<dim3(256, 1, 3), 256, SM_GEMM>>>(g);
    ca_scores_kernel<<<dim3(S_ / 64, T_ / 128, B_ * H_), 256, SM_GEMM>>>(qh, kh, sc);
    softmax_kernel<<<B_ * H_ * T_, 256>>>(sc, sch);
    attn_v_kernel<<<dim3(1, T_ / 128, B_ * H_), 256, SM_GEMM>>>(sch, vth, oh, S_);
    g.j[0] = { oh, wh + WCAO_OFF, ca_out_b, x1, tmp, nullptr, D_, D_, D_, D_, 8, 1, 0 };
    gemm_nt<<<dim3(256, 1, 1), 256, SM_GEMM>>>(g);
    ln_kernel<<<B_ * T_, 128>>>(tmp, ln2_s, ln2_b, x2, x2h, 0);

    // --- FFN ---
    g.j[0] = { x2h, wh + WL1_OFF, lin1_b, nullptr, nullptr, ffnh, D_, D_, F_, D_, 32, 1, 1 };
    gemm_nt<<<dim3(1024, 1, 1), 256, SM_GEMM>>>(g);
    g.j[0] = { ffnh, wh + WL2_OFF, lin2_b, x2, tmp, nullptr, F_, F_, D_, F_, 8, 1, 0 };
    gemm_nt<<<dim3(256, 1, 1), 256, SM_GEMM>>>(g);
    ln_kernel<<<B_ * T_, 128>>>(tmp, ln3_s, ln3_b, (float*)d_out, nullptr, 1);
}